// round 1
// baseline (speedup 1.0000x reference)
#include <cuda_runtime.h>

#define Bq 4
#define Cc 32
#define Tt 1024
#define Uu 32
#define Hh 128
#define JT 256

// Scratch (no allocations allowed) — device globals.
__device__ float g_qp[Bq * Tt * Uu];   // q + bh, layout (B,T,U)
__device__ float g_kT[Bq * Uu * Tt];   // k transposed, layout (B,U,T)
__device__ float g_rm[Bq * Tt];        // per-row max of e
__device__ float g_rs[Bq * Tt];        // per-row sum of exp(e-m)
__device__ float g_y [Bq * Tt * Cc];   // LN1 output, layout (B,T,C)

__device__ __forceinline__ float tanh_fast(float x) {
    float y;
    asm("tanh.approx.f32 %0, %1;" : "=f"(y) : "f"(x));
    return y;
}

// ---------------------------------------------------------------------------
// Kernel A: qp[b,t,u] = bh[u] + sum_c x[b,c,t]*Wt[c,u]
//           kT[b,u,t] =         sum_c x[b,c,t]*Wx[c,u]
// grid = B * (T/128), 256 threads
// ---------------------------------------------------------------------------
__global__ void __launch_bounds__(256) k_prep(const float* __restrict__ x,
                                              const float* __restrict__ Wt,
                                              const float* __restrict__ Wx,
                                              const float* __restrict__ bh) {
    __shared__ float xs[Cc * 128];
    __shared__ float Wts[Cc * 33];
    __shared__ float Wxs[Cc * 33];
    __shared__ float bhs[Uu];

    int b  = blockIdx.x / (Tt / 128);
    int t0 = (blockIdx.x % (Tt / 128)) * 128;
    int tid = threadIdx.x;

    for (int i = tid; i < Cc * 128; i += 256) {
        int c = i >> 7, tl = i & 127;
        xs[i] = x[b * Cc * Tt + c * Tt + t0 + tl];
    }
    for (int i = tid; i < Cc * Uu; i += 256) {
        int c = i >> 5, u = i & 31;
        Wts[c * 33 + u] = Wt[i];
        Wxs[c * 33 + u] = Wx[i];
    }
    if (tid < Uu) bhs[tid] = bh[tid];
    __syncthreads();

    {   // qp: thread owns fixed u = tid&31, sweeps tl
        int u = tid & 31;
        float wcol[Cc];
        #pragma unroll
        for (int c = 0; c < Cc; c++) wcol[c] = Wts[c * 33 + u];
        #pragma unroll
        for (int k = 0; k < 16; k++) {
            int tl = (tid >> 5) + k * 8;
            float acc = bhs[u];
            #pragma unroll
            for (int c = 0; c < Cc; c++) acc += xs[c * 128 + tl] * wcol[c];
            g_qp[(b * Tt + t0 + tl) * Uu + u] = acc;
        }
    }
    {   // kT: thread owns fixed tl = tid&127, sweeps u
        int tl = tid & 127;
        float xcol[Cc];
        #pragma unroll
        for (int c = 0; c < Cc; c++) xcol[c] = xs[c * 128 + tl];
        #pragma unroll
        for (int k = 0; k < 16; k++) {
            int u = (tid >> 7) + k * 2;
            float acc = 0.f;
            #pragma unroll
            for (int c = 0; c < Cc; c++) acc += xcol[c] * Wxs[c * 33 + u];
            g_kT[b * Uu * Tt + u * Tt + t0 + tl] = acc;
        }
    }
}

// ---------------------------------------------------------------------------
// Kernel B (hot): e[b,i,j] = ba + sum_u Wa[u]*tanh(qp[i,u]+k[j,u]),
// stored raw into the a-region of d_out; online row max/sum.
// warp per row i, lanes sweep j. grid = B*(T/8), 256 threads.
// ---------------------------------------------------------------------------
__global__ void __launch_bounds__(256) k_scores(const float* __restrict__ Wa,
                                                const float* __restrict__ ba,
                                                float* __restrict__ e_out) {
    __shared__ float ks[Uu * JT];     // transposed K tile: ks[u][jj]
    __shared__ float qps[8 * Uu];

    int b  = blockIdx.x / (Tt / 8);
    int i0 = (blockIdx.x % (Tt / 8)) * 8;
    int tid = threadIdx.x, w = tid >> 5, lane = tid & 31;

    qps[tid] = g_qp[(b * Tt + i0) * Uu + tid];   // 8 rows x 32
    float war[Uu];
    #pragma unroll
    for (int u = 0; u < Uu; u++) war[u] = Wa[u];
    float bav = ba[0];
    __syncthreads();

    float qpr[Uu];
    #pragma unroll
    for (int u = 0; u < Uu; u++) qpr[u] = qps[w * Uu + u];

    int i = i0 + w;
    float m = -1e30f, s = 0.f;
    float* erow = e_out + (size_t)(b * Tt + i) * Tt;
    const float* kbase = g_kT + b * Uu * Tt;

    for (int j0 = 0; j0 < Tt; j0 += JT) {
        __syncthreads();
        for (int i4 = tid; i4 < Uu * JT / 4; i4 += 256) {
            int u = i4 / (JT / 4), q = i4 % (JT / 4);
            float4 v4 = *(const float4*)&kbase[u * Tt + j0 + q * 4];
            *(float4*)&ks[u * JT + q * 4] = v4;
        }
        __syncthreads();

        #pragma unroll
        for (int jt = 0; jt < JT / 32; jt++) {
            int jj = jt * 32 + lane;
            float a0 = 0.f, a1 = 0.f, a2 = 0.f, a3 = 0.f;
            #pragma unroll
            for (int u = 0; u < Uu; u += 4) {
                a0 += war[u    ] * tanh_fast(qpr[u    ] + ks[(u    ) * JT + jj]);
                a1 += war[u + 1] * tanh_fast(qpr[u + 1] + ks[(u + 1) * JT + jj]);
                a2 += war[u + 2] * tanh_fast(qpr[u + 2] + ks[(u + 2) * JT + jj]);
                a3 += war[u + 3] * tanh_fast(qpr[u + 3] + ks[(u + 3) * JT + jj]);
            }
            float e = (a0 + a1) + (a2 + a3) + bav;
            erow[j0 + jj] = e;                       // raw score, coalesced
            float mn = fmaxf(m, e);
            s = s * __expf(m - mn) + __expf(e - mn); // branchless online
            m = mn;
        }
    }

    // merge lanes
    #pragma unroll
    for (int off = 16; off; off >>= 1) {
        float mo = __shfl_xor_sync(0xffffffffu, m, off);
        float so = __shfl_xor_sync(0xffffffffu, s, off);
        float mn = fmaxf(m, mo);
        s = s * __expf(m - mn) + so * __expf(mo - mn);
        m = mn;
    }
    if (lane == 0) { g_rm[b * Tt + i] = m; g_rs[b * Tt + i] = s; }
}

// ---------------------------------------------------------------------------
// Kernel C1: a = exp(e-m)/(s+1e-5) in place; v = a @ xt; y = LN1(x+v) -> g_y
// warp per row t. grid = B*(T/8), 256 threads.
// ---------------------------------------------------------------------------
__global__ void __launch_bounds__(256) k_av(const float* __restrict__ x,
                                            float* __restrict__ a_io,
                                            const float* __restrict__ g1,
                                            const float* __restrict__ be1) {
    __shared__ float xts[Cc * 128];   // xts[c][jj]
    __shared__ float xrow[8 * Cc];    // x[b,:,t] for the 8 rows
    __shared__ float g1s[Cc], be1s[Cc];
    __shared__ float vz[8][33];       // z = x + v per row

    int b  = blockIdx.x / (Tt / 8);
    int t0 = (blockIdx.x % (Tt / 8)) * 8;
    int tid = threadIdx.x, w = tid >> 5, lane = tid & 31;

    {
        int c = tid & 31, ww = tid >> 5;
        xrow[ww * Cc + c] = x[b * Cc * Tt + c * Tt + t0 + ww];
    }
    if (tid < Cc) { g1s[tid] = g1[tid]; be1s[tid] = be1[tid]; }

    int t = t0 + w;
    float m = g_rm[b * Tt + t], s = g_rs[b * Tt + t];
    float inv = 1.f / (s + 1e-5f);

    float vacc[Cc];
    #pragma unroll
    for (int c = 0; c < Cc; c++) vacc[c] = 0.f;

    float* arow = a_io + (size_t)(b * Tt + t) * Tt;
    const float* xb = x + b * Cc * Tt;

    for (int j0 = 0; j0 < Tt; j0 += 128) {
        __syncthreads();
        for (int i4 = tid; i4 < Cc * 32; i4 += 256) {
            int c = i4 >> 5, q = i4 & 31;
            *(float4*)&xts[c * 128 + q * 4] = *(const float4*)&xb[c * Tt + j0 + q * 4];
        }
        __syncthreads();
        #pragma unroll
        for (int jt = 0; jt < 4; jt++) {
            int jj = jt * 32 + lane;
            float e = arow[j0 + jj];
            float p = __expf(e - m) * inv;
            arow[j0 + jj] = p;                         // normalized a
            #pragma unroll
            for (int c = 0; c < Cc; c++) vacc[c] += p * xts[c * 128 + jj];
        }
    }

    // reduce v across lanes (all lanes end with full sums)
    #pragma unroll
    for (int c = 0; c < Cc; c++) {
        #pragma unroll
        for (int off = 16; off; off >>= 1)
            vacc[c] += __shfl_xor_sync(0xffffffffu, vacc[c], off);
    }
    if (lane == 0) {
        #pragma unroll
        for (int c = 0; c < Cc; c++) vz[w][c] = xrow[w * Cc + c] + vacc[c];
    }
    __syncwarp();

    float mean = 0.f;
    #pragma unroll
    for (int c = 0; c < Cc; c++) mean += vz[w][c];
    mean *= (1.f / Cc);
    float var = 0.f;
    #pragma unroll
    for (int c = 0; c < Cc; c++) { float d = vz[w][c] - mean; var += d * d; }
    var = var * (1.f / Cc) + 1e-14f;
    float rstd = rsqrtf(var);

    g_y[(b * Tt + t) * Cc + lane] =
        (vz[w][lane] - mean) * rstd * g1s[lane] + be1s[lane];
}

// ---------------------------------------------------------------------------
// Kernel C2: FF + residual + LN2 -> y2 (B,C,T). warp per token t.
// grid = B*(T/8), 256 threads.
// ---------------------------------------------------------------------------
__global__ void __launch_bounds__(256) k_ff(const float* __restrict__ W1,
                                            const float* __restrict__ b1,
                                            const float* __restrict__ W2,
                                            const float* __restrict__ b2,
                                            const float* __restrict__ g2,
                                            const float* __restrict__ be2,
                                            float* __restrict__ y2) {
    __shared__ float W1T[Cc * 129];   // W1T[c][h], padded
    __shared__ float W2s[Cc * Hh];    // W2[c][h]
    __shared__ float b1s[Hh], b2s[Cc], g2s[Cc], be2s[Cc];
    __shared__ float z2s[8][33];

    int b  = blockIdx.x / (Tt / 8);
    int t0 = (blockIdx.x % (Tt / 8)) * 8;
    int tid = threadIdx.x, w = tid >> 5, lane = tid & 31;

    for (int i = tid; i < Hh * Cc; i += 256) {
        int h = i >> 5, c = i & 31;
        W1T[c * 129 + h] = W1[i];     // W1 is (H,C) row-major
        W2s[i] = W2[i];               // W2 is (C,H) row-major
    }
    if (tid < Hh) b1s[tid] = b1[tid];
    if (tid < Cc) { b2s[tid] = b2[tid]; g2s[tid] = g2[tid]; be2s[tid] = be2[tid]; }
    __syncthreads();

    int t = t0 + w;
    const float* yr = g_y + (b * Tt + t) * Cc;
    float y[Cc];
    #pragma unroll
    for (int c = 0; c < Cc; c++) y[c] = yr[c];

    float h1[4];
    #pragma unroll
    for (int k = 0; k < 4; k++) {
        int h = lane + k * 32;
        float acc = b1s[h];
        #pragma unroll
        for (int c = 0; c < Cc; c++) acc += y[c] * W1T[c * 129 + h];
        h1[k] = fmaxf(acc, 0.f);
    }

    float h2p[Cc];
    #pragma unroll
    for (int c = 0; c < Cc; c++) {
        float acc = 0.f;
        #pragma unroll
        for (int k = 0; k < 4; k++) acc += h1[k] * W2s[c * Hh + lane + k * 32];
        h2p[c] = acc;
    }
    #pragma unroll
    for (int c = 0; c < Cc; c++) {
        #pragma unroll
        for (int off = 16; off; off >>= 1)
            h2p[c] += __shfl_xor_sync(0xffffffffu, h2p[c], off);
    }

    if (lane == 0) {
        #pragma unroll
        for (int c = 0; c < Cc; c++) z2s[w][c] = y[c] + h2p[c] + b2s[c];
    }
    __syncwarp();

    float mean = 0.f;
    #pragma unroll
    for (int c = 0; c < Cc; c++) mean += z2s[w][c];
    mean *= (1.f / Cc);
    float var = 0.f;
    #pragma unroll
    for (int c = 0; c < Cc; c++) { float d = z2s[w][c] - mean; var += d * d; }
    var = var * (1.f / Cc) + 1e-14f;
    float rstd = rsqrtf(var);

    y2[b * Cc * Tt + lane * Tt + t] =
        (z2s[w][lane] - mean) * rstd * g2s[lane] + be2s[lane];
}

// ---------------------------------------------------------------------------
extern "C" void kernel_launch(void* const* d_in, const int* in_sizes, int n_in,
                              void* d_out, int out_size) {
    (void)in_sizes; (void)n_in; (void)out_size;
    const float* x   = (const float*)d_in[0];
    const float* Wt  = (const float*)d_in[1];
    const float* Wx  = (const float*)d_in[2];
    const float* bh  = (const float*)d_in[3];
    const float* Wa  = (const float*)d_in[4];
    const float* ba  = (const float*)d_in[5];
    const float* g1  = (const float*)d_in[6];
    const float* be1 = (const float*)d_in[7];
    const float* W1  = (const float*)d_in[8];
    const float* b1  = (const float*)d_in[9];
    const float* W2  = (const float*)d_in[10];
    const float* b2  = (const float*)d_in[11];
    const float* g2  = (const float*)d_in[12];
    const float* be2 = (const float*)d_in[13];

    float* out = (float*)d_out;
    float* y2  = out;                    // (B,C,T) = 131072 floats
    float* a   = out + Bq * Cc * Tt;     // (B,T,T) = 4194304 floats

    k_prep  <<<Bq * (Tt / 128), 256>>>(x, Wt, Wx, bh);
    k_scores<<<Bq * (Tt / 8),   256>>>(Wa, ba, a);
    k_av    <<<Bq * (Tt / 8),   256>>>(x, a, g1, be1);
    k_ff    <<<Bq * (Tt / 8),   256>>>(W1, b1, W2, b2, g2, be2, y2);
}

// round 2
// speedup vs baseline: 1.1921x; 1.1921x over previous
#include <cuda_runtime.h>
#include <cuda_fp16.h>

#define Bq 4
#define Cc 32
#define Tt 1024
#define Uu 32
#define Hh 128

// Scratch — device globals (no allocations allowed).
__device__ float    g_qp[Bq * Tt * Uu];            // q + bh, (B,T,U) f32
__device__ unsigned g_kh_u[Bq * Uu * Tt / 2];      // k as f16, (B,U,T)
__device__ unsigned g_xh_u[Bq * Cc * Tt / 2];      // x as f16, (B,C,T)
__device__ unsigned g_e_u [Bq * Tt * (Tt / 2)];    // raw scores e as f16, (B,T,T)
__device__ float    g_rm[Bq * Tt];                 // per-row max of e
__device__ float    g_y [Bq * Tt * Cc];            // LN1 output, (B,T,C)

__device__ __forceinline__ __half2 tanh2(__half2 x) {
    unsigned xi = *reinterpret_cast<unsigned*>(&x), ri;
    asm("tanh.approx.f16x2 %0, %1;" : "=r"(ri) : "r"(xi));
    return *reinterpret_cast<__half2*>(&ri);
}
__device__ __forceinline__ __half2 u2h2(unsigned u) { return *reinterpret_cast<__half2*>(&u); }
__device__ __forceinline__ unsigned h22u(__half2 h) { return *reinterpret_cast<unsigned*>(&h); }

// ---------------------------------------------------------------------------
// Kernel A: qp[b,t,u] = bh[u] + sum_c x[b,c,t]*Wt[c,u]     (f32)
//           kh[b,u,t] =         sum_c x[b,c,t]*Wx[c,u]     (f16)
//           xh[b,c,t] = f16(x)
// grid = B * (T/128), 256 threads
// ---------------------------------------------------------------------------
__global__ void __launch_bounds__(256) k_prep(const float* __restrict__ x,
                                              const float* __restrict__ Wt,
                                              const float* __restrict__ Wx,
                                              const float* __restrict__ bh) {
    __shared__ float xs[Cc * 128];
    __shared__ float Wts[Cc * 33];
    __shared__ float Wxs[Cc * 33];
    __shared__ float bhs[Uu];

    int b  = blockIdx.x / (Tt / 128);
    int t0 = (blockIdx.x % (Tt / 128)) * 128;
    int tid = threadIdx.x;

    __half* xh = (__half*)g_xh_u;
    __half* kh = (__half*)g_kh_u;

    for (int i = tid; i < Cc * 128; i += 256) {
        int c = i >> 7, tl = i & 127;
        float v = x[b * Cc * Tt + c * Tt + t0 + tl];
        xs[i] = v;
        xh[b * Cc * Tt + c * Tt + t0 + tl] = __float2half(v);
    }
    for (int i = tid; i < Cc * Uu; i += 256) {
        int c = i >> 5, u = i & 31;
        Wts[c * 33 + u] = Wt[i];
        Wxs[c * 33 + u] = Wx[i];
    }
    if (tid < Uu) bhs[tid] = bh[tid];
    __syncthreads();

    {   // qp: thread owns fixed u = tid&31, sweeps tl
        int u = tid & 31;
        float wcol[Cc];
        #pragma unroll
        for (int c = 0; c < Cc; c++) wcol[c] = Wts[c * 33 + u];
        #pragma unroll
        for (int k = 0; k < 16; k++) {
            int tl = (tid >> 5) + k * 8;
            float acc = bhs[u];
            #pragma unroll
            for (int c = 0; c < Cc; c++) acc += xs[c * 128 + tl] * wcol[c];
            g_qp[(b * Tt + t0 + tl) * Uu + u] = acc;
        }
    }
    {   // kh: thread owns fixed tl = tid&127, sweeps u
        int tl = tid & 127;
        float xcol[Cc];
        #pragma unroll
        for (int c = 0; c < Cc; c++) xcol[c] = xs[c * 128 + tl];
        #pragma unroll
        for (int k = 0; k < 16; k++) {
            int u = (tid >> 7) + k * 2;
            float acc = 0.f;
            #pragma unroll
            for (int c = 0; c < Cc; c++) acc += xcol[c] * Wxs[c * 33 + u];
            kh[b * Uu * Tt + u * Tt + t0 + tl] = __float2half(acc);
        }
    }
}

// ---------------------------------------------------------------------------
// Kernel B (hot): e[b,i,j] = ba + sum_u Wa[u]*tanh(qp[i,u]+k[j,u])  in f16x2.
// Stores raw e (f16) to g_e, tracks row max only.
// warp per row i, lanes sweep j-pairs. grid = B*(T/8), 256 threads.
// ---------------------------------------------------------------------------
__global__ void __launch_bounds__(256) k_scores(const float* __restrict__ Wa,
                                                const float* __restrict__ ba) {
    __shared__ __half2 khs[Uu][128];   // K tile: 256 j's = 128 pairs, 16KB

    int b  = blockIdx.x / (Tt / 8);
    int i0 = (blockIdx.x % (Tt / 8)) * 8;
    int tid = threadIdx.x, w = tid >> 5, lane = tid & 31;
    int i = i0 + w;

    const float* qrow = g_qp + (size_t)(b * Tt + i) * Uu;
    __half2 q2[Uu], wa2[Uu];
    #pragma unroll
    for (int u = 0; u < Uu; u++) {
        q2[u]  = __float2half2_rn(qrow[u]);
        wa2[u] = __float2half2_rn(Wa[u]);
    }
    __half2 ba2 = __float2half2_rn(ba[0]);
    __half2 m2  = __float2half2_rn(-60000.f);
    __half2 z2  = __float2half2_rn(0.f);

    const uint4* kb4 = (const uint4*)g_kh_u + (size_t)b * Uu * Tt / 8;
    unsigned* erow = g_e_u + (size_t)(b * Tt + i) * (Tt / 2);

    for (int j0p = 0; j0p < Tt / 2; j0p += 128) {
        __syncthreads();
        for (int idx = tid; idx < Uu * 32; idx += 256) {
            int u = idx >> 5, g = idx & 31;
            ((uint4*)khs)[u * 32 + g] = kb4[u * 128 + (j0p >> 2) + g];
        }
        __syncthreads();

        #pragma unroll
        for (int jt = 0; jt < 4; jt++) {
            int pj = jt * 32 + lane;
            __half2 acc = z2;
            #pragma unroll
            for (int u = 0; u < Uu; u++)
                acc = __hfma2(wa2[u], tanh2(__hadd2(q2[u], khs[u][pj])), acc);
            __half2 e2 = __hadd2(acc, ba2);
            m2 = __hmax2(m2, e2);
            erow[j0p + pj] = h22u(e2);
        }
    }

    float m = fmaxf(__low2float(m2), __high2float(m2));
    #pragma unroll
    for (int off = 16; off; off >>= 1)
        m = fmaxf(m, __shfl_xor_sync(0xffffffffu, m, off));
    if (lane == 0) g_rm[b * Tt + i] = m;
}

// ---------------------------------------------------------------------------
// Kernel C1: s = sum exp(e); v = sum exp(e)*x (f16 HFMA2, f32 flush);
//            a = exp(e)/(s + 1e-5*exp(m));  y = LN1(x + v/den) -> g_y
// warp per row t. grid = B*(T/8), 256 threads.
// ---------------------------------------------------------------------------
__global__ void __launch_bounds__(256) k_av(const float* __restrict__ x,
                                            float* __restrict__ a_out,
                                            const float* __restrict__ g1,
                                            const float* __restrict__ be1) {
    __shared__ __half2 xh2s[Cc][256];   // x tile: 512 j's = 256 pairs, 32KB

    int b  = blockIdx.x / (Tt / 8);
    int t0 = (blockIdx.x % (Tt / 8)) * 8;
    int tid = threadIdx.x, w = tid >> 5, lane = tid & 31;
    int t = t0 + w;
    size_t row = (size_t)b * Tt + t;

    float m = g_rm[row];
    const unsigned* erow_u = g_e_u + row * (Tt / 2);
    const uint4*    erow4  = (const uint4*)erow_u;

    float s = 0.f;
    float vaccf[Cc];
    #pragma unroll
    for (int c = 0; c < Cc; c++) vaccf[c] = 0.f;
    __half2 zero2 = __float2half2_rn(0.f);

    for (int chunk = 0; chunk < 2; chunk++) {
        __syncthreads();
        for (int idx = tid; idx < Cc * 64; idx += 256) {
            int c = idx >> 6, g = idx & 63;
            ((uint4*)xh2s)[c * 64 + g] =
                ((const uint4*)g_xh_u)[(size_t)b * Cc * Tt / 8 + c * 128 + chunk * 64 + g];
        }
        __syncthreads();

        __half2 vacc2[Cc];
        #pragma unroll
        for (int c = 0; c < Cc; c++) vacc2[c] = zero2;

        #pragma unroll
        for (int q = 0; q < 2; q++) {
            int g  = chunk * 64 + q * 32 + lane;      // uint4-group in row
            int lp = (q * 32 + lane) * 4;             // pair index in chunk
            uint4 e4 = erow4[g];
            __half2 p2[4];
            unsigned eu[4] = {e4.x, e4.y, e4.z, e4.w};
            #pragma unroll
            for (int r = 0; r < 4; r++) {
                float2 f = __half22float2(u2h2(eu[r]));
                float px = __expf(f.x), py = __expf(f.y);
                s += px + py;
                p2[r] = __floats2half2_rn(px, py);
            }
            #pragma unroll
            for (int c = 0; c < Cc; c++) {
                uint4 xv = *(const uint4*)&xh2s[c][lp];
                vacc2[c] = __hfma2(p2[0], u2h2(xv.x), vacc2[c]);
                vacc2[c] = __hfma2(p2[1], u2h2(xv.y), vacc2[c]);
                vacc2[c] = __hfma2(p2[2], u2h2(xv.z), vacc2[c]);
                vacc2[c] = __hfma2(p2[3], u2h2(xv.w), vacc2[c]);
            }
        }
        #pragma unroll
        for (int c = 0; c < Cc; c++) {
            float2 f = __half22float2(vacc2[c]);
            vaccf[c] += f.x + f.y;
        }
    }

    // reduce s and v across lanes
    #pragma unroll
    for (int off = 16; off; off >>= 1)
        s += __shfl_xor_sync(0xffffffffu, s, off);
    float den = s + 1e-5f * __expf(m);
    float inv = 1.f / den;

    float mine = 0.f;
    #pragma unroll
    for (int c = 0; c < Cc; c++) {
        float tot = vaccf[c];
        #pragma unroll
        for (int off = 16; off; off >>= 1)
            tot += __shfl_xor_sync(0xffffffffu, tot, off);
        if (lane == c) mine = tot;
    }

    // z = x + v ; LN1 (lane = channel)
    float xres = x[(size_t)b * Cc * Tt + (size_t)lane * Tt + t];
    float z = xres + mine * inv;
    float sum = z;
    #pragma unroll
    for (int off = 16; off; off >>= 1)
        sum += __shfl_xor_sync(0xffffffffu, sum, off);
    float mean = sum * (1.f / Cc);
    float d = z - mean;
    float vv = d * d;
    #pragma unroll
    for (int off = 16; off; off >>= 1)
        vv += __shfl_xor_sync(0xffffffffu, vv, off);
    float rstd = rsqrtf(vv * (1.f / Cc) + 1e-14f);
    g_y[row * Cc + lane] = d * rstd * g1[lane] + be1[lane];

    // sweep 2: write normalized a
    float* arow = a_out + row * Tt;
    #pragma unroll
    for (int q = 0; q < 16; q++) {
        int idx = q * 32 + lane;
        float2 f = __half22float2(u2h2(erow_u[idx]));
        ((float2*)arow)[idx] = make_float2(__expf(f.x) * inv, __expf(f.y) * inv);
    }
}

// ---------------------------------------------------------------------------
// Kernel C2: FF + residual + LN2 -> y2 (B,C,T). 16 tokens/block, shuffle-light.
// grid = B*(T/16) = 256 blocks, 256 threads.
// ---------------------------------------------------------------------------
__global__ void __launch_bounds__(256) k_ff(const float* __restrict__ W1,
                                            const float* __restrict__ b1,
                                            const float* __restrict__ W2,
                                            const float* __restrict__ b2,
                                            const float* __restrict__ g2,
                                            const float* __restrict__ be2,
                                            float* __restrict__ y2) {
    __shared__ float W1T[Cc * 129];   // W1T[c][h]
    __shared__ float W2p[Cc * 129];   // W2[c][h]
    __shared__ float h1s[16 * 129];
    __shared__ float ys[16 * 33];
    __shared__ float b1s[Hh], b2s[Cc], g2s[Cc], be2s[Cc];

    int b  = blockIdx.x / (Tt / 16);
    int t0 = (blockIdx.x % (Tt / 16)) * 16;
    int tid = threadIdx.x, w = tid >> 5, lane = tid & 31;

    for (int i = tid; i < Hh * Cc; i += 256) {
        int h = i >> 5, c = i & 31;
        W1T[c * 129 + h] = W1[i];                 // W1 (H,C) row-major
        int c2 = i >> 7, h2 = i & 127;
        W2p[c2 * 129 + h2] = W2[i];               // W2 (C,H) row-major
    }
    for (int i = tid; i < 16 * Cc; i += 256) {
        int tok = i >> 5, c = i & 31;
        ys[tok * 33 + c] = g_y[((size_t)b * Tt + t0 + tok) * Cc + c];
    }
    if (tid < Hh) b1s[tid] = b1[tid];
    if (tid < Cc) { b2s[tid] = b2[tid]; g2s[tid] = g2[tid]; be2s[tid] = be2[tid]; }
    __syncthreads();

    // GEMM1 + relu: warp w handles tokens 2w, 2w+1
    #pragma unroll
    for (int tk = 0; tk < 2; tk++) {
        int tok = 2 * w + tk;
        float yv[Cc];
        #pragma unroll
        for (int c = 0; c < Cc; c++) yv[c] = ys[tok * 33 + c];
        #pragma unroll
        for (int k = 0; k < 4; k++) {
            int h = lane + 32 * k;
            float acc = b1s[h];
            #pragma unroll
            for (int c = 0; c < Cc; c++) acc += yv[c] * W1T[c * 129 + h];
            h1s[tok * 129 + h] = fmaxf(acc, 0.f);
        }
    }
    __syncthreads();

    // GEMM2 + residual + LN2: lane = channel
    #pragma unroll
    for (int tk = 0; tk < 2; tk++) {
        int tok = 2 * w + tk;
        int t = t0 + tok;
        float acc = 0.f;
        #pragma unroll
        for (int h = 0; h < Hh; h++)
            acc += h1s[tok * 129 + h] * W2p[lane * 129 + h];
        float z = ys[tok * 33 + lane] + acc + b2s[lane];

        float sum = z;
        #pragma unroll
        for (int off = 16; off; off >>= 1)
            sum += __shfl_xor_sync(0xffffffffu, sum, off);
        float mean = sum * (1.f / Cc);
        float d = z - mean;
        float vv = d * d;
        #pragma unroll
        for (int off = 16; off; off >>= 1)
            vv += __shfl_xor_sync(0xffffffffu, vv, off);
        float rstd = rsqrtf(vv * (1.f / Cc) + 1e-14f);
        y2[(size_t)b * Cc * Tt + (size_t)lane * Tt + t] = d * rstd * g2s[lane] + be2s[lane];
    }
}

// ---------------------------------------------------------------------------
extern "C" void kernel_launch(void* const* d_in, const int* in_sizes, int n_in,
                              void* d_out, int out_size) {
    (void)in_sizes; (void)n_in; (void)out_size;
    const float* x   = (const float*)d_in[0];
    const float* Wt  = (const float*)d_in[1];
    const float* Wx  = (const float*)d_in[2];
    const float* bh  = (const float*)d_in[3];
    const float* Wa  = (const float*)d_in[4];
    const float* ba  = (const float*)d_in[5];
    const float* g1  = (const float*)d_in[6];
    const float* be1 = (const float*)d_in[7];
    const float* W1  = (const float*)d_in[8];
    const float* b1  = (const float*)d_in[9];
    const float* W2  = (const float*)d_in[10];
    const float* b2  = (const float*)d_in[11];
    const float* g2  = (const float*)d_in[12];
    const float* be2 = (const float*)d_in[13];

    float* out = (float*)d_out;
    float* y2  = out;                    // (B,C,T) = 131072 floats
    float* a   = out + Bq * Cc * Tt;     // (B,T,T) = 4194304 floats

    k_prep  <<<Bq * (Tt / 128), 256>>>(x, Wt, Wx, bh);
    k_scores<<<Bq * (Tt / 8),   256>>>(Wa, ba);
    k_av    <<<Bq * (Tt / 8),   256>>>(x, a, g1, be1);
    k_ff    <<<Bq * (Tt / 16),  256>>>(W1, b1, W2, b2, g2, be2, y2);
}

// round 3
// speedup vs baseline: 1.3282x; 1.1141x over previous
#include <cuda_runtime.h>
#include <cuda_fp16.h>

#define Bq 4
#define Cc 32
#define Tt 1024
#define Uu 32
#define Hh 128

// Scratch — device globals (no allocations allowed).
__device__ float    g_qp[Bq * Tt * Uu];            // q + bh, (B,T,U) f32
__device__ unsigned g_kh_u[Bq * Uu * Tt / 2];      // k as f16, (B,U,T)
__device__ unsigned g_xh_u[Bq * Cc * Tt / 2];      // x as f16, (B,C,T)
__device__ unsigned g_e_u [Bq * Tt * (Tt / 2)];    // raw scores e as f16, (B,T,T)
__device__ float    g_rm[Bq * Tt];                 // per-row max of e
__device__ float    g_y [Bq * Tt * Cc];            // LN1 output, (B,T,C)

__device__ __forceinline__ __half2 tanh2(__half2 x) {
    unsigned xi = *reinterpret_cast<unsigned*>(&x), ri;
    asm("tanh.approx.f16x2 %0, %1;" : "=r"(ri) : "r"(xi));
    return *reinterpret_cast<__half2*>(&ri);
}
__device__ __forceinline__ __half2 u2h2(unsigned u) { return *reinterpret_cast<__half2*>(&u); }
__device__ __forceinline__ unsigned h22u(__half2 h) { return *reinterpret_cast<unsigned*>(&h); }

// ---------------------------------------------------------------------------
// Kernel A: qp[b,t,u] = bh[u] + sum_c x[b,c,t]*Wt[c,u]     (f32)
//           kh[b,u,t] =         sum_c x[b,c,t]*Wx[c,u]     (f16)
//           xh[b,c,t] = f16(x)
// ---------------------------------------------------------------------------
__global__ void __launch_bounds__(256) k_prep(const float* __restrict__ x,
                                              const float* __restrict__ Wt,
                                              const float* __restrict__ Wx,
                                              const float* __restrict__ bh) {
    __shared__ float xs[Cc * 128];
    __shared__ float Wts[Cc * 33];
    __shared__ float Wxs[Cc * 33];
    __shared__ float bhs[Uu];

    int b  = blockIdx.x / (Tt / 128);
    int t0 = (blockIdx.x % (Tt / 128)) * 128;
    int tid = threadIdx.x;

    __half* xh = (__half*)g_xh_u;
    __half* kh = (__half*)g_kh_u;

    for (int i = tid; i < Cc * 128; i += 256) {
        int c = i >> 7, tl = i & 127;
        float v = x[b * Cc * Tt + c * Tt + t0 + tl];
        xs[i] = v;
        xh[b * Cc * Tt + c * Tt + t0 + tl] = __float2half(v);
    }
    for (int i = tid; i < Cc * Uu; i += 256) {
        int c = i >> 5, u = i & 31;
        Wts[c * 33 + u] = Wt[i];
        Wxs[c * 33 + u] = Wx[i];
    }
    if (tid < Uu) bhs[tid] = bh[tid];
    __syncthreads();

    {
        int u = tid & 31;
        float wcol[Cc];
        #pragma unroll
        for (int c = 0; c < Cc; c++) wcol[c] = Wts[c * 33 + u];
        #pragma unroll
        for (int k = 0; k < 16; k++) {
            int tl = (tid >> 5) + k * 8;
            float acc = bhs[u];
            #pragma unroll
            for (int c = 0; c < Cc; c++) acc += xs[c * 128 + tl] * wcol[c];
            g_qp[(b * Tt + t0 + tl) * Uu + u] = acc;
        }
    }
    {
        int tl = tid & 127;
        float xcol[Cc];
        #pragma unroll
        for (int c = 0; c < Cc; c++) xcol[c] = xs[c * 128 + tl];
        #pragma unroll
        for (int k = 0; k < 16; k++) {
            int u = (tid >> 7) + k * 2;
            float acc = 0.f;
            #pragma unroll
            for (int c = 0; c < Cc; c++) acc += xcol[c] * Wxs[c * 33 + u];
            kh[b * Uu * Tt + u * Tt + t0 + tl] = __float2half(acc);
        }
    }
}

// ---------------------------------------------------------------------------
// Kernel B (hot): e[b,i,j] = ba + sum_u Wa[u]*tanh(qp[i,u]+k[j,u])  f16x2.
// ---------------------------------------------------------------------------
__global__ void __launch_bounds__(256) k_scores(const float* __restrict__ Wa,
                                                const float* __restrict__ ba) {
    __shared__ __half2 khs[Uu][128];   // 256 j's = 128 pairs, 16KB

    int b  = blockIdx.x / (Tt / 8);
    int i0 = (blockIdx.x % (Tt / 8)) * 8;
    int tid = threadIdx.x, w = tid >> 5, lane = tid & 31;
    int i = i0 + w;

    const float* qrow = g_qp + (size_t)(b * Tt + i) * Uu;
    __half2 q2[Uu], wa2[Uu];
    #pragma unroll
    for (int u = 0; u < Uu; u++) {
        q2[u]  = __float2half2_rn(qrow[u]);
        wa2[u] = __float2half2_rn(Wa[u]);
    }
    __half2 ba2 = __float2half2_rn(ba[0]);
    __half2 m2  = __float2half2_rn(-60000.f);
    __half2 z2  = __float2half2_rn(0.f);

    const uint4* kb4 = (const uint4*)g_kh_u + (size_t)b * Uu * Tt / 8;
    unsigned* erow = g_e_u + (size_t)(b * Tt + i) * (Tt / 2);

    for (int j0p = 0; j0p < Tt / 2; j0p += 128) {
        __syncthreads();
        for (int idx = tid; idx < Uu * 32; idx += 256) {
            int u = idx >> 5, g = idx & 31;
            ((uint4*)khs)[u * 32 + g] = kb4[u * 128 + (j0p >> 2) + g];
        }
        __syncthreads();

        #pragma unroll
        for (int jt = 0; jt < 4; jt++) {
            int pj = jt * 32 + lane;
            __half2 acc = z2;
            #pragma unroll
            for (int u = 0; u < Uu; u++)
                acc = __hfma2(wa2[u], tanh2(__hadd2(q2[u], khs[u][pj])), acc);
            __half2 e2 = __hadd2(acc, ba2);
            m2 = __hmax2(m2, e2);
            erow[j0p + pj] = h22u(e2);
        }
    }

    float m = fmaxf(__low2float(m2), __high2float(m2));
    #pragma unroll
    for (int off = 16; off; off >>= 1)
        m = fmaxf(m, __shfl_xor_sync(0xffffffffu, m, off));
    if (lane == 0) g_rm[b * Tt + i] = m;
}

// ---------------------------------------------------------------------------
// Kernel C1: 2 rows per warp. s = sum exp(e); v = sum exp(e)*x (f16 acc);
//            a = exp(e)/den ; y = LN1(x + v/den) -> g_y
// grid = B*(T/16), 256 threads (8 warps x 2 rows = 16 rows/block).
// ---------------------------------------------------------------------------
__global__ void __launch_bounds__(256) k_av(const float* __restrict__ x,
                                            float* __restrict__ a_out,
                                            const float* __restrict__ g1,
                                            const float* __restrict__ be1) {
    __shared__ __half2 xh2s[Cc][256];   // 512 j's = 256 pairs, 32KB

    int b  = blockIdx.x / (Tt / 16);
    int t0 = (blockIdx.x % (Tt / 16)) * 16;
    int tid = threadIdx.x, w = tid >> 5, lane = tid & 31;
    int tA = t0 + 2 * w, tB = tA + 1;
    size_t rowA = (size_t)b * Tt + tA, rowB = rowA + 1;

    const unsigned* eAu = g_e_u + rowA * (Tt / 2);
    const unsigned* eBu = g_e_u + rowB * (Tt / 2);
    const uint4* eA4 = (const uint4*)eAu;
    const uint4* eB4 = (const uint4*)eBu;

    float sA = 0.f, sB = 0.f;
    __half2 zero2 = __float2half2_rn(0.f);
    __half2 vA[Cc], vB[Cc];
    #pragma unroll
    for (int c = 0; c < Cc; c++) { vA[c] = zero2; vB[c] = zero2; }

    for (int chunk = 0; chunk < 2; chunk++) {
        __syncthreads();
        for (int idx = tid; idx < Cc * 64; idx += 256) {
            int c = idx >> 6, g = idx & 63;
            ((uint4*)xh2s)[c * 64 + g] =
                ((const uint4*)g_xh_u)[(size_t)b * Cc * Tt / 8 + c * 128 + chunk * 64 + g];
        }
        __syncthreads();

        #pragma unroll
        for (int q = 0; q < 2; q++) {
            int g   = chunk * 64 + q * 32 + lane;
            int lp4 = q * 32 + lane;              // uint4 index within tile row
            uint4 ea = eA4[g], eb = eB4[g];
            unsigned eua[4] = {ea.x, ea.y, ea.z, ea.w};
            unsigned eub[4] = {eb.x, eb.y, eb.z, eb.w};
            __half2 pA[4], pB[4];
            #pragma unroll
            for (int r = 0; r < 4; r++) {
                float2 fa = __half22float2(u2h2(eua[r]));
                float2 fb = __half22float2(u2h2(eub[r]));
                float pax = __expf(fa.x), pay = __expf(fa.y);
                float pbx = __expf(fb.x), pby = __expf(fb.y);
                sA += pax + pay; sB += pbx + pby;
                pA[r] = __floats2half2_rn(pax, pay);
                pB[r] = __floats2half2_rn(pbx, pby);
            }
            #pragma unroll
            for (int c = 0; c < Cc; c++) {
                uint4 xv = ((const uint4*)&xh2s[c][0])[lp4];
                vA[c] = __hfma2(pA[0], u2h2(xv.x), vA[c]);
                vA[c] = __hfma2(pA[1], u2h2(xv.y), vA[c]);
                vA[c] = __hfma2(pA[2], u2h2(xv.z), vA[c]);
                vA[c] = __hfma2(pA[3], u2h2(xv.w), vA[c]);
                vB[c] = __hfma2(pB[0], u2h2(xv.x), vB[c]);
                vB[c] = __hfma2(pB[1], u2h2(xv.y), vB[c]);
                vB[c] = __hfma2(pB[2], u2h2(xv.z), vB[c]);
                vB[c] = __hfma2(pB[3], u2h2(xv.w), vB[c]);
            }
        }
    }

    float vfA[Cc], vfB[Cc];
    #pragma unroll
    for (int c = 0; c < Cc; c++) {
        float2 fa = __half22float2(vA[c]); vfA[c] = fa.x + fa.y;
        float2 fb = __half22float2(vB[c]); vfB[c] = fb.x + fb.y;
    }

    #pragma unroll
    for (int off = 16; off; off >>= 1) {
        sA += __shfl_xor_sync(0xffffffffu, sA, off);
        sB += __shfl_xor_sync(0xffffffffu, sB, off);
    }
    float invA = 1.f / (sA + 1e-5f * __expf(g_rm[rowA]));
    float invB = 1.f / (sB + 1e-5f * __expf(g_rm[rowB]));

    float mineA = 0.f, mineB = 0.f;
    #pragma unroll
    for (int c = 0; c < Cc; c++) {
        float ta = vfA[c], tb = vfB[c];
        #pragma unroll
        for (int off = 16; off; off >>= 1) {
            ta += __shfl_xor_sync(0xffffffffu, ta, off);
            tb += __shfl_xor_sync(0xffffffffu, tb, off);
        }
        if (lane == c) { mineA = ta; mineB = tb; }
    }

    // LN1 for both rows (lane = channel)
    const float* xb = x + (size_t)b * Cc * Tt + (size_t)lane * Tt;
    #pragma unroll
    for (int r = 0; r < 2; r++) {
        int t = (r == 0) ? tA : tB;
        size_t row = (r == 0) ? rowA : rowB;
        float z = xb[t] + ((r == 0) ? mineA * invA : mineB * invB);
        float sum = z;
        #pragma unroll
        for (int off = 16; off; off >>= 1)
            sum += __shfl_xor_sync(0xffffffffu, sum, off);
        float mean = sum * (1.f / Cc);
        float d = z - mean;
        float vv = d * d;
        #pragma unroll
        for (int off = 16; off; off >>= 1)
            vv += __shfl_xor_sync(0xffffffffu, vv, off);
        float rstd = rsqrtf(vv * (1.f / Cc) + 1e-14f);
        g_y[row * Cc + lane] = d * rstd * g1[lane] + be1[lane];
    }

    // sweep 2: write normalized a for both rows
    float* arowA = a_out + rowA * Tt;
    float* arowB = a_out + rowB * Tt;
    #pragma unroll
    for (int q = 0; q < 16; q++) {
        int idx = q * 32 + lane;
        float2 fa = __half22float2(u2h2(eAu[idx]));
        float2 fb = __half22float2(u2h2(eBu[idx]));
        ((float2*)arowA)[idx] = make_float2(__expf(fa.x) * invA, __expf(fa.y) * invA);
        ((float2*)arowB)[idx] = make_float2(__expf(fb.x) * invB, __expf(fb.y) * invB);
    }
}

// ---------------------------------------------------------------------------
// Kernel C2: FF + residual + LN2 -> y2 (B,C,T). 4 tokens/warp, 128 thr/block.
// grid = B*(T/16) = 256 blocks.
// ---------------------------------------------------------------------------
__global__ void __launch_bounds__(128) k_ff(const float* __restrict__ W1,
                                            const float* __restrict__ b1,
                                            const float* __restrict__ W2,
                                            const float* __restrict__ b2,
                                            const float* __restrict__ g2,
                                            const float* __restrict__ be2,
                                            float* __restrict__ y2) {
    __shared__ float W1T[Cc * 129];   // W1T[c][h]
    __shared__ float W2p[Cc * 129];   // W2p[c][h]
    __shared__ float h1s[16 * 132];
    __shared__ float ys[16 * 33];
    __shared__ float b1s[Hh], b2s[Cc], g2s[Cc], be2s[Cc];

    int b  = blockIdx.x / (Tt / 16);
    int t0 = (blockIdx.x % (Tt / 16)) * 16;
    int tid = threadIdx.x, w = tid >> 5, lane = tid & 31;

    for (int i = tid; i < Hh * Cc; i += 128) {
        int h = i >> 5, c = i & 31;
        W1T[c * 129 + h] = W1[i];                 // W1 (H,C) row-major
        int c2 = i >> 7, h2 = i & 127;
        W2p[c2 * 129 + h2] = W2[i];               // W2 (C,H) row-major
    }
    for (int i = tid; i < 16 * Cc; i += 128) {
        int tok = i >> 5, c = i & 31;
        ys[tok * 33 + c] = g_y[((size_t)b * Tt + t0 + tok) * Cc + c];
    }
    if (tid < Hh) b1s[tid] = b1[tid];
    if (tid < Cc) { b2s[tid] = b2[tid]; g2s[tid] = g2[tid]; be2s[tid] = be2[tid]; }
    __syncthreads();

    int tokbase = 4 * w;

    // GEMM1 + relu: 4 tokens, weight LDS reused across tokens
    float acc[4][4];
    #pragma unroll
    for (int k = 0; k < 4; k++) {
        float bb = b1s[lane + 32 * k];
        #pragma unroll
        for (int tk = 0; tk < 4; tk++) acc[k][tk] = bb;
    }
    #pragma unroll
    for (int c = 0; c < Cc; c++) {
        float yv[4];
        #pragma unroll
        for (int tk = 0; tk < 4; tk++) yv[tk] = ys[(tokbase + tk) * 33 + c];
        #pragma unroll
        for (int k = 0; k < 4; k++) {
            float wv = W1T[c * 129 + lane + 32 * k];
            #pragma unroll
            for (int tk = 0; tk < 4; tk++) acc[k][tk] += yv[tk] * wv;
        }
    }
    #pragma unroll
    for (int k = 0; k < 4; k++)
        #pragma unroll
        for (int tk = 0; tk < 4; tk++)
            h1s[(tokbase + tk) * 132 + lane + 32 * k] = fmaxf(acc[k][tk], 0.f);
    __syncwarp();

    // GEMM2 (lane = channel), weight LDS reused across 4 tokens
    float a2[4] = {0.f, 0.f, 0.f, 0.f};
    #pragma unroll 4
    for (int h = 0; h < Hh; h++) {
        float wv = W2p[lane * 129 + h];
        #pragma unroll
        for (int tk = 0; tk < 4; tk++)
            a2[tk] += h1s[(tokbase + tk) * 132 + h] * wv;
    }

    #pragma unroll
    for (int tk = 0; tk < 4; tk++) {
        int tok = tokbase + tk;
        int t = t0 + tok;
        float z = ys[tok * 33 + lane] + a2[tk] + b2s[lane];
        float sum = z;
        #pragma unroll
        for (int off = 16; off; off >>= 1)
            sum += __shfl_xor_sync(0xffffffffu, sum, off);
        float mean = sum * (1.f / Cc);
        float d = z - mean;
        float vv = d * d;
        #pragma unroll
        for (int off = 16; off; off >>= 1)
            vv += __shfl_xor_sync(0xffffffffu, vv, off);
        float rstd = rsqrtf(vv * (1.f / Cc) + 1e-14f);
        y2[(size_t)b * Cc * Tt + (size_t)lane * Tt + t] = d * rstd * g2s[lane] + be2s[lane];
    }
}

// ---------------------------------------------------------------------------
extern "C" void kernel_launch(void* const* d_in, const int* in_sizes, int n_in,
                              void* d_out, int out_size) {
    (void)in_sizes; (void)n_in; (void)out_size;
    const float* x   = (const float*)d_in[0];
    const float* Wt  = (const float*)d_in[1];
    const float* Wx  = (const float*)d_in[2];
    const float* bh  = (const float*)d_in[3];
    const float* Wa  = (const float*)d_in[4];
    const float* ba  = (const float*)d_in[5];
    const float* g1  = (const float*)d_in[6];
    const float* be1 = (const float*)d_in[7];
    const float* W1  = (const float*)d_in[8];
    const float* b1  = (const float*)d_in[9];
    const float* W2  = (const float*)d_in[10];
    const float* b2  = (const float*)d_in[11];
    const float* g2  = (const float*)d_in[12];
    const float* be2 = (const float*)d_in[13];

    float* out = (float*)d_out;
    float* y2  = out;                    // (B,C,T) = 131072 floats
    float* a   = out + Bq * Cc * Tt;     // (B,T,T) = 4194304 floats

    k_prep  <<<Bq * (Tt / 128), 256>>>(x, Wt, Wx, bh);
    k_scores<<<Bq * (Tt / 8),   256>>>(Wa, ba);
    k_av    <<<Bq * (Tt / 16),  256>>>(x, a, g1, be1);
    k_ff    <<<Bq * (Tt / 16),  128>>>(W1, b1, W2, b2, g2, be2, y2);
}

// round 4
// speedup vs baseline: 1.3508x; 1.0171x over previous
#include <cuda_runtime.h>
#include <cuda_fp16.h>

#define Bq 4
#define Cc 32
#define Tt 1024
#define Uu 32
#define Hh 128

// Scratch — device globals (no allocations allowed).
__device__ float    g_qp[Bq * Tt * Uu];            // q + bh, (B,T,U) f32
__device__ unsigned g_kh_u[Bq * Uu * Tt / 2];      // k as f16, (B,U,T)
__device__ unsigned g_xh_u[Bq * Cc * Tt / 2];      // x as f16, (B,C,T)
__device__ unsigned g_e_u [Bq * Tt * (Tt / 2)];    // raw scores e as f16, (B,T,T)
__device__ float    g_rm[Bq * Tt];                 // per-row max of e

__device__ __forceinline__ __half2 tanh2(__half2 x) {
    unsigned xi = *reinterpret_cast<unsigned*>(&x), ri;
    asm("tanh.approx.f16x2 %0, %1;" : "=r"(ri) : "r"(xi));
    return *reinterpret_cast<__half2*>(&ri);
}
__device__ __forceinline__ __half2 u2h2(unsigned u) { return *reinterpret_cast<__half2*>(&u); }
__device__ __forceinline__ unsigned h22u(__half2 h) { return *reinterpret_cast<unsigned*>(&h); }

// ---------------------------------------------------------------------------
// Kernel A: qp[b,t,u] = bh[u] + sum_c x[b,c,t]*Wt[c,u]     (f32)
//           kh[b,u,t] =         sum_c x[b,c,t]*Wx[c,u]     (f16)
//           xh[b,c,t] = f16(x)
// ---------------------------------------------------------------------------
__global__ void __launch_bounds__(256) k_prep(const float* __restrict__ x,
                                              const float* __restrict__ Wt,
                                              const float* __restrict__ Wx,
                                              const float* __restrict__ bh) {
    __shared__ float xs[Cc * 128];
    __shared__ float Wts[Cc * 33];
    __shared__ float Wxs[Cc * 33];
    __shared__ float bhs[Uu];

    int b  = blockIdx.x / (Tt / 128);
    int t0 = (blockIdx.x % (Tt / 128)) * 128;
    int tid = threadIdx.x;

    __half* xh = (__half*)g_xh_u;
    __half* kh = (__half*)g_kh_u;

    for (int i = tid; i < Cc * 128; i += 256) {
        int c = i >> 7, tl = i & 127;
        float v = x[b * Cc * Tt + c * Tt + t0 + tl];
        xs[i] = v;
        xh[b * Cc * Tt + c * Tt + t0 + tl] = __float2half(v);
    }
    for (int i = tid; i < Cc * Uu; i += 256) {
        int c = i >> 5, u = i & 31;
        Wts[c * 33 + u] = Wt[i];
        Wxs[c * 33 + u] = Wx[i];
    }
    if (tid < Uu) bhs[tid] = bh[tid];
    __syncthreads();

    {
        int u = tid & 31;
        float wcol[Cc];
        #pragma unroll
        for (int c = 0; c < Cc; c++) wcol[c] = Wts[c * 33 + u];
        #pragma unroll
        for (int k = 0; k < 16; k++) {
            int tl = (tid >> 5) + k * 8;
            float acc = bhs[u];
            #pragma unroll
            for (int c = 0; c < Cc; c++) acc += xs[c * 128 + tl] * wcol[c];
            g_qp[(b * Tt + t0 + tl) * Uu + u] = acc;
        }
    }
    {
        int tl = tid & 127;
        float xcol[Cc];
        #pragma unroll
        for (int c = 0; c < Cc; c++) xcol[c] = xs[c * 128 + tl];
        #pragma unroll
        for (int k = 0; k < 16; k++) {
            int u = (tid >> 7) + k * 2;
            float acc = 0.f;
            #pragma unroll
            for (int c = 0; c < Cc; c++) acc += xcol[c] * Wxs[c * 33 + u];
            kh[b * Uu * Tt + u * Tt + t0 + tl] = __float2half(acc);
        }
    }
}

// ---------------------------------------------------------------------------
// Kernel B (hot): e[b,i,j] = ba + sum_u Wa[u]*tanh(qp[i,u]+k[j,u])  f16x2.
// ---------------------------------------------------------------------------
__global__ void __launch_bounds__(256) k_scores(const float* __restrict__ Wa,
                                                const float* __restrict__ ba) {
    __shared__ __half2 khs[Uu][128];   // 256 j's = 128 pairs, 16KB

    int b  = blockIdx.x / (Tt / 8);
    int i0 = (blockIdx.x % (Tt / 8)) * 8;
    int tid = threadIdx.x, w = tid >> 5, lane = tid & 31;
    int i = i0 + w;

    const float* qrow = g_qp + (size_t)(b * Tt + i) * Uu;
    __half2 q2[Uu], wa2[Uu];
    #pragma unroll
    for (int u = 0; u < Uu; u++) {
        q2[u]  = __float2half2_rn(qrow[u]);
        wa2[u] = __float2half2_rn(Wa[u]);
    }
    __half2 ba2 = __float2half2_rn(ba[0]);
    __half2 m2  = __float2half2_rn(-60000.f);
    __half2 z2  = __float2half2_rn(0.f);

    const uint4* kb4 = (const uint4*)g_kh_u + (size_t)b * Uu * Tt / 8;
    unsigned* erow = g_e_u + (size_t)(b * Tt + i) * (Tt / 2);

    for (int j0p = 0; j0p < Tt / 2; j0p += 128) {
        __syncthreads();
        for (int idx = tid; idx < Uu * 32; idx += 256) {
            int u = idx >> 5, g = idx & 31;
            ((uint4*)khs)[u * 32 + g] = kb4[u * 128 + (j0p >> 2) + g];
        }
        __syncthreads();

        #pragma unroll
        for (int jt = 0; jt < 4; jt++) {
            int pj = jt * 32 + lane;
            __half2 acc0 = z2, acc1 = z2;
            #pragma unroll
            for (int u = 0; u < Uu; u += 2) {
                acc0 = __hfma2(wa2[u    ], tanh2(__hadd2(q2[u    ], khs[u    ][pj])), acc0);
                acc1 = __hfma2(wa2[u + 1], tanh2(__hadd2(q2[u + 1], khs[u + 1][pj])), acc1);
            }
            __half2 e2 = __hadd2(__hadd2(acc0, acc1), ba2);
            m2 = __hmax2(m2, e2);
            erow[j0p + pj] = h22u(e2);
        }
    }

    float m = fmaxf(__low2float(m2), __high2float(m2));
    #pragma unroll
    for (int off = 16; off; off >>= 1)
        m = fmaxf(m, __shfl_xor_sync(0xffffffffu, m, off));
    if (lane == 0) g_rm[b * Tt + i] = m;
}

// ---------------------------------------------------------------------------
// Fused Kernel C: attention-apply + LN1 + FF + LN2, 16 tokens/block.
// Dynamic smem. grid = B*(T/16) = 256 blocks, 256 threads.
// ---------------------------------------------------------------------------
#define OFF_XT   0                          // __half2 xh2s[Cc][256]   32768 B
#define OFF_W1T  32768                      // float W1T[Cc*129]       16512 B
#define OFF_W2P  (OFF_W1T + 16512)          // float W2p[Cc*129]       16512 B
#define OFF_YS   (OFF_W2P + 16512)          // float ys[16*33]          2112 B
#define OFF_H1   (OFF_YS + 2112)            // float h1s[16*132]        8448 B
#define OFF_B1   (OFF_H1 + 8448)            // float b1s[128]            512 B
#define OFF_B2   (OFF_B1 + 512)             // float b2s[32]             128 B
#define OFF_G2   (OFF_B2 + 128)             // float g2s[32]             128 B
#define OFF_BE2  (OFF_G2 + 128)             // float be2s[32]            128 B
#define SMEM_AVFF (OFF_BE2 + 128)           // 77056 B

__global__ void __launch_bounds__(256) k_av_ff(const float* __restrict__ x,
                                               float* __restrict__ a_out,
                                               const float* __restrict__ g1,
                                               const float* __restrict__ be1,
                                               const float* __restrict__ W1,
                                               const float* __restrict__ b1,
                                               const float* __restrict__ W2,
                                               const float* __restrict__ b2,
                                               const float* __restrict__ g2,
                                               const float* __restrict__ be2,
                                               float* __restrict__ y2) {
    extern __shared__ char dyn[];
    __half2 (*xh2s)[256] = (__half2 (*)[256])(dyn + OFF_XT);
    float* W1T  = (float*)(dyn + OFF_W1T);
    float* W2p  = (float*)(dyn + OFF_W2P);
    float* ys   = (float*)(dyn + OFF_YS);
    float* h1s  = (float*)(dyn + OFF_H1);
    float* b1s  = (float*)(dyn + OFF_B1);
    float* b2s  = (float*)(dyn + OFF_B2);
    float* g2s  = (float*)(dyn + OFF_G2);
    float* be2s = (float*)(dyn + OFF_BE2);

    int b  = blockIdx.x / (Tt / 16);
    int t0 = (blockIdx.x % (Tt / 16)) * 16;
    int tid = threadIdx.x, w = tid >> 5, lane = tid & 31;
    int tA = t0 + 2 * w, tB = tA + 1;
    size_t rowA = (size_t)b * Tt + tA, rowB = rowA + 1;

    // FF weight staging — issued first, hidden under the attention sweep.
    for (int i = tid; i < Hh * Cc; i += 256) {
        int h = i >> 5, c = i & 31;
        W1T[c * 129 + h] = W1[i];                 // W1 (H,C) row-major
        int c2 = i >> 7, h2 = i & 127;
        W2p[c2 * 129 + h2] = W2[i];               // W2 (C,H) row-major
    }
    if (tid < Hh) b1s[tid] = b1[tid];
    if (tid < Cc) { b2s[tid] = b2[tid]; g2s[tid] = g2[tid]; be2s[tid] = be2[tid]; }

    const unsigned* eAu = g_e_u + rowA * (Tt / 2);
    const unsigned* eBu = g_e_u + rowB * (Tt / 2);
    const uint4* eA4 = (const uint4*)eAu;
    const uint4* eB4 = (const uint4*)eBu;

    float sA = 0.f, sB = 0.f;
    __half2 zero2 = __float2half2_rn(0.f);
    __half2 vA[Cc], vB[Cc];
    #pragma unroll
    for (int c = 0; c < Cc; c++) { vA[c] = zero2; vB[c] = zero2; }

    for (int chunk = 0; chunk < 2; chunk++) {
        __syncthreads();
        for (int idx = tid; idx < Cc * 64; idx += 256) {
            int c = idx >> 6, g = idx & 63;
            ((uint4*)xh2s)[c * 64 + g] =
                ((const uint4*)g_xh_u)[(size_t)b * Cc * Tt / 8 + c * 128 + chunk * 64 + g];
        }
        __syncthreads();

        #pragma unroll
        for (int q = 0; q < 2; q++) {
            int g   = chunk * 64 + q * 32 + lane;
            int lp4 = q * 32 + lane;
            uint4 ea = eA4[g], eb = eB4[g];
            unsigned eua[4] = {ea.x, ea.y, ea.z, ea.w};
            unsigned eub[4] = {eb.x, eb.y, eb.z, eb.w};
            __half2 pA[4], pB[4];
            #pragma unroll
            for (int r = 0; r < 4; r++) {
                float2 fa = __half22float2(u2h2(eua[r]));
                float2 fb = __half22float2(u2h2(eub[r]));
                float pax = __expf(fa.x), pay = __expf(fa.y);
                float pbx = __expf(fb.x), pby = __expf(fb.y);
                sA += pax + pay; sB += pbx + pby;
                pA[r] = __floats2half2_rn(pax, pay);
                pB[r] = __floats2half2_rn(pbx, pby);
            }
            #pragma unroll
            for (int c = 0; c < Cc; c++) {
                uint4 xv = ((const uint4*)&xh2s[c][0])[lp4];
                vA[c] = __hfma2(pA[0], u2h2(xv.x), vA[c]);
                vA[c] = __hfma2(pA[1], u2h2(xv.y), vA[c]);
                vA[c] = __hfma2(pA[2], u2h2(xv.z), vA[c]);
                vA[c] = __hfma2(pA[3], u2h2(xv.w), vA[c]);
                vB[c] = __hfma2(pB[0], u2h2(xv.x), vB[c]);
                vB[c] = __hfma2(pB[1], u2h2(xv.y), vB[c]);
                vB[c] = __hfma2(pB[2], u2h2(xv.z), vB[c]);
                vB[c] = __hfma2(pB[3], u2h2(xv.w), vB[c]);
            }
        }
    }

    float vfA[Cc], vfB[Cc];
    #pragma unroll
    for (int c = 0; c < Cc; c++) {
        float2 fa = __half22float2(vA[c]); vfA[c] = fa.x + fa.y;
        float2 fb = __half22float2(vB[c]); vfB[c] = fb.x + fb.y;
    }

    #pragma unroll
    for (int off = 16; off; off >>= 1) {
        sA += __shfl_xor_sync(0xffffffffu, sA, off);
        sB += __shfl_xor_sync(0xffffffffu, sB, off);
    }
    float invA = 1.f / (sA + 1e-5f * __expf(g_rm[rowA]));
    float invB = 1.f / (sB + 1e-5f * __expf(g_rm[rowB]));

    float mineA = 0.f, mineB = 0.f;
    #pragma unroll
    for (int c = 0; c < Cc; c++) {
        float ta = vfA[c], tb = vfB[c];
        #pragma unroll
        for (int off = 16; off; off >>= 1) {
            ta += __shfl_xor_sync(0xffffffffu, ta, off);
            tb += __shfl_xor_sync(0xffffffffu, tb, off);
        }
        if (lane == c) { mineA = ta; mineB = tb; }
    }

    // LN1 for both rows (lane = channel) -> ys in smem
    const float* xb = x + (size_t)b * Cc * Tt + (size_t)lane * Tt;
    #pragma unroll
    for (int r = 0; r < 2; r++) {
        int t = (r == 0) ? tA : tB;
        float z = xb[t] + ((r == 0) ? mineA * invA : mineB * invB);
        float sum = z;
        #pragma unroll
        for (int off = 16; off; off >>= 1)
            sum += __shfl_xor_sync(0xffffffffu, sum, off);
        float mean = sum * (1.f / Cc);
        float d = z - mean;
        float vv = d * d;
        #pragma unroll
        for (int off = 16; off; off >>= 1)
            vv += __shfl_xor_sync(0xffffffffu, vv, off);
        float rstd = rsqrtf(vv * (1.f / Cc) + 1e-14f);
        ys[(2 * w + r) * 33 + lane] = d * rstd * g1[lane] + be1[lane];
    }
    __syncwarp();

    // ---- FF phase (intra-warp: this warp's 2 tokens) ----
    int tokbase = 2 * w;
    float acc[4][2];
    #pragma unroll
    for (int k = 0; k < 4; k++) {
        float bb = b1s[lane + 32 * k];
        acc[k][0] = bb; acc[k][1] = bb;
    }
    #pragma unroll
    for (int c = 0; c < Cc; c++) {
        float yv0 = ys[tokbase * 33 + c];
        float yv1 = ys[(tokbase + 1) * 33 + c];
        #pragma unroll
        for (int k = 0; k < 4; k++) {
            float wv = W1T[c * 129 + lane + 32 * k];
            acc[k][0] += yv0 * wv;
            acc[k][1] += yv1 * wv;
        }
    }
    #pragma unroll
    for (int k = 0; k < 4; k++) {
        h1s[tokbase * 132 + lane + 32 * k]       = fmaxf(acc[k][0], 0.f);
        h1s[(tokbase + 1) * 132 + lane + 32 * k] = fmaxf(acc[k][1], 0.f);
    }
    __syncwarp();

    float a2[2] = {0.f, 0.f};
    #pragma unroll 4
    for (int h = 0; h < Hh; h++) {
        float wv = W2p[lane * 129 + h];
        a2[0] += h1s[tokbase * 132 + h] * wv;
        a2[1] += h1s[(tokbase + 1) * 132 + h] * wv;
    }

    #pragma unroll
    for (int tk = 0; tk < 2; tk++) {
        int tok = tokbase + tk;
        int t = t0 + tok;
        float z = ys[tok * 33 + lane] + a2[tk] + b2s[lane];
        float sum = z;
        #pragma unroll
        for (int off = 16; off; off >>= 1)
            sum += __shfl_xor_sync(0xffffffffu, sum, off);
        float mean = sum * (1.f / Cc);
        float d = z - mean;
        float vv = d * d;
        #pragma unroll
        for (int off = 16; off; off >>= 1)
            vv += __shfl_xor_sync(0xffffffffu, vv, off);
        float rstd = rsqrtf(vv * (1.f / Cc) + 1e-14f);
        y2[(size_t)b * Cc * Tt + (size_t)lane * Tt + t] = d * rstd * g2s[lane] + be2s[lane];
    }

    // ---- write normalized a (bulk DRAM traffic last) ----
    float* arowA = a_out + rowA * Tt;
    float* arowB = a_out + rowB * Tt;
    #pragma unroll
    for (int q = 0; q < 16; q++) {
        int idx = q * 32 + lane;
        float2 fa = __half22float2(u2h2(eAu[idx]));
        float2 fb = __half22float2(u2h2(eBu[idx]));
        ((float2*)arowA)[idx] = make_float2(__expf(fa.x) * invA, __expf(fa.y) * invA);
        ((float2*)arowB)[idx] = make_float2(__expf(fb.x) * invB, __expf(fb.y) * invB);
    }
}

// ---------------------------------------------------------------------------
extern "C" void kernel_launch(void* const* d_in, const int* in_sizes, int n_in,
                              void* d_out, int out_size) {
    (void)in_sizes; (void)n_in; (void)out_size;
    const float* x   = (const float*)d_in[0];
    const float* Wt  = (const float*)d_in[1];
    const float* Wx  = (const float*)d_in[2];
    const float* bh  = (const float*)d_in[3];
    const float* Wa  = (const float*)d_in[4];
    const float* ba  = (const float*)d_in[5];
    const float* g1  = (const float*)d_in[6];
    const float* be1 = (const float*)d_in[7];
    const float* W1  = (const float*)d_in[8];
    const float* b1  = (const float*)d_in[9];
    const float* W2  = (const float*)d_in[10];
    const float* b2  = (const float*)d_in[11];
    const float* g2  = (const float*)d_in[12];
    const float* be2 = (const float*)d_in[13];

    float* out = (float*)d_out;
    float* y2  = out;                    // (B,C,T) = 131072 floats
    float* a   = out + Bq * Cc * Tt;     // (B,T,T) = 4194304 floats

    cudaFuncSetAttribute(k_av_ff, cudaFuncAttributeMaxDynamicSharedMemorySize, SMEM_AVFF);

    k_prep  <<<Bq * (Tt / 128), 256>>>(x, Wt, Wx, bh);
    k_scores<<<Bq * (Tt / 8),   256>>>(Wa, ba);
    k_av_ff <<<Bq * (Tt / 16),  256, SMEM_AVFF>>>(x, a, g1, be1, W1, b1, W2, b2, g2, be2, y2);
}

// round 5
// speedup vs baseline: 1.4783x; 1.0943x over previous
#include <cuda_runtime.h>
#include <cuda_fp16.h>

#define Bq 4
#define Cc 32
#define Tt 1024
#define Uu 32
#define Hh 128
#define PCH 128                 // pairs per j-chunk (256 j)
#define NCH 4                   // chunks

// Scratch — device globals (no allocations allowed).
__device__ float    g_qp[Bq * Tt * Uu];            // q + bh, (B,T,U) f32
__device__ unsigned g_kh_u[Bq * Uu * Tt / 2];      // k as f16, (B,U,T)
__device__ unsigned g_xh_u[Bq * Cc * Tt / 2];      // x as f16, (B,C,T)
__device__ unsigned g_e_u [Bq * Tt * (Tt / 2)];    // raw scores e as f16, (B,T,T)

__device__ __forceinline__ __half2 tanh2(__half2 x) {
    unsigned xi = *reinterpret_cast<unsigned*>(&x), ri;
    asm("tanh.approx.f16x2 %0, %1;" : "=r"(ri) : "r"(xi));
    return *reinterpret_cast<__half2*>(&ri);
}
__device__ __forceinline__ __half2 u2h2(unsigned u) { return *reinterpret_cast<__half2*>(&u); }
__device__ __forceinline__ unsigned h22u(__half2 h) { return *reinterpret_cast<unsigned*>(&h); }

// ---------------------------------------------------------------------------
// k_prep v2: 32 tokens/block, grid = B*(T/32) = 128, 256 threads.
// qp[b,t,u] (f32), kh[b,u,t] (f16), xh[b,c,t] (f16)
// ---------------------------------------------------------------------------
__global__ void __launch_bounds__(256) k_prep(const float* __restrict__ x,
                                              const float* __restrict__ Wt,
                                              const float* __restrict__ Wx,
                                              const float* __restrict__ bh) {
    __shared__ float xs[Cc][32];
    __shared__ float Wts[Cc][33];
    __shared__ float Wxs[Cc][33];
    __shared__ float bhs[Uu];
    __shared__ __half kts[Uu][34];   // k f16 tile, pad 34 (17-word rows, conflict-free)

    int b  = blockIdx.x >> 5;
    int t0 = (blockIdx.x & 31) * 32;
    int tid = threadIdx.x;
    int u = tid & 31, tlg = tid >> 5;

    for (int i = tid; i < Cc * 32; i += 256) {
        int c = i >> 5, tl = i & 31;
        xs[c][tl] = x[b * Cc * Tt + c * Tt + t0 + tl];
    }
    for (int i = tid; i < Cc * Uu; i += 256) {
        int c = i >> 5, uu = i & 31;
        Wts[c][uu] = Wt[i];
        Wxs[c][uu] = Wx[i];
    }
    if (tid < Uu) bhs[tid] = bh[tid];
    __syncthreads();

    #pragma unroll
    for (int rep = 0; rep < 4; rep++) {
        int tl = tlg + rep * 8;
        float accq = bhs[u], acck = 0.f;
        #pragma unroll
        for (int c = 0; c < Cc; c++) {
            float xv = xs[c][tl];
            accq += xv * Wts[c][u];
            acck += xv * Wxs[c][u];
        }
        g_qp[(b * Tt + t0 + tl) * Uu + u] = accq;
        kts[u][tl] = __float2half(acck);
    }
    __syncthreads();

    // coalesced f16 writes: kh rows (from kts) and xh rows (from xs)
    {
        int r = tid >> 3, g = tid & 7;          // 32 rows x 8 groups of 4 halves
        __half* kh = (__half*)g_kh_u;
        __half* xh = (__half*)g_xh_u;
        unsigned* khrow = (unsigned*)(kh + (size_t)b * Uu * Tt + (size_t)r * Tt + t0);
        khrow[2 * g]     = *(unsigned*)&kts[r][4 * g];
        khrow[2 * g + 1] = *(unsigned*)&kts[r][4 * g + 2];
        unsigned* xhrow = (unsigned*)(xh + (size_t)b * Cc * Tt + (size_t)r * Tt + t0);
        __half2 h0 = __floats2half2_rn(xs[r][4 * g],     xs[r][4 * g + 1]);
        __half2 h1 = __floats2half2_rn(xs[r][4 * g + 2], xs[r][4 * g + 3]);
        xhrow[2 * g]     = h22u(h0);
        xhrow[2 * g + 1] = h22u(h1);
    }
}

// ---------------------------------------------------------------------------
// k_main: fused scores + softmax + v + LN1 + FF + LN2 + a-write.
// grid = B*(T/16) = 256 blocks, 256 threads; warp w owns tokens t0+w, t0+w+8.
// ---------------------------------------------------------------------------
#define OFF_KHS  0                                  // __half2 [32][128]  16384
#define OFF_XHS  16384                              // __half2 [32][128]  16384
#define OFF_PS   32768                              // __half2 [16][128]   8192
#define OFF_WAS  40960                              // __half2 [32]         128
#define OFF_QSM  41088                              // float   [16*32]     2048
#define OFF_W1T  43136                              // float   [32*129]   16512
#define OFF_W2P  59648                              // float   [32*129]   16512
#define OFF_YS   76160                              // float   [16*33]     2112
#define OFF_H1   78272                              // float   [16*132]    8448
#define OFF_B1   86720                              // float   [128]        512
#define OFF_B2   87232                              // float   [32]         128
#define OFF_G2   87360                              // float   [32]         128
#define OFF_BE2  87488                              // float   [32]         128
#define SMEM_MAIN 87616

__global__ void __launch_bounds__(256, 2) k_main(const float* __restrict__ x,
                                                 float* __restrict__ a_out,
                                                 const float* __restrict__ Wa,
                                                 const float* __restrict__ ba,
                                                 const float* __restrict__ g1,
                                                 const float* __restrict__ be1,
                                                 const float* __restrict__ W1,
                                                 const float* __restrict__ b1,
                                                 const float* __restrict__ W2,
                                                 const float* __restrict__ b2,
                                                 const float* __restrict__ g2,
                                                 const float* __restrict__ be2,
                                                 float* __restrict__ y2) {
    extern __shared__ char dyn[];
    __half2 (*khs)[PCH] = (__half2 (*)[PCH])(dyn + OFF_KHS);
    __half2 (*xhs)[PCH] = (__half2 (*)[PCH])(dyn + OFF_XHS);
    __half2* psm  = (__half2*)(dyn + OFF_PS);
    __half2* was  = (__half2*)(dyn + OFF_WAS);
    float* qsm  = (float*)(dyn + OFF_QSM);
    float* W1T  = (float*)(dyn + OFF_W1T);
    float* W2p  = (float*)(dyn + OFF_W2P);
    float* ys   = (float*)(dyn + OFF_YS);
    float* h1s  = (float*)(dyn + OFF_H1);
    float* b1s  = (float*)(dyn + OFF_B1);
    float* b2s  = (float*)(dyn + OFF_B2);
    float* g2s  = (float*)(dyn + OFF_G2);
    float* be2s = (float*)(dyn + OFF_BE2);

    int b  = blockIdx.x / (Tt / 16);
    int t0 = (blockIdx.x % (Tt / 16)) * 16;
    int tid = threadIdx.x, w = tid >> 5, lane = tid & 31;
    int tA = t0 + w, tB = t0 + w + 8;
    size_t rowA = (size_t)b * Tt + tA, rowB = (size_t)b * Tt + tB;

    // ---- staging (hidden under first chunk latency) ----
    for (int i = tid; i < Hh * Cc; i += 256) {
        int h = i >> 5, c = i & 31;
        W1T[c * 129 + h] = W1[i];                 // W1 (H,C) row-major
        int c2 = i >> 7, h2i = i & 127;
        W2p[c2 * 129 + h2i] = W2[i];              // W2 (C,H) row-major
    }
    for (int i = tid; i < 16 * Uu; i += 256)
        qsm[i] = g_qp[((size_t)b * Tt + t0 + (i >> 5)) * Uu + (i & 31)];
    if (tid < Uu) was[tid] = __float2half2_rn(Wa[tid]);
    if (tid < Hh) b1s[tid] = b1[tid];
    if (tid < Cc) { b2s[tid] = b2[tid]; g2s[tid] = g2[tid]; be2s[tid] = be2[tid]; }
    __syncthreads();

    __half2 qA[Uu], qB[Uu];
    #pragma unroll
    for (int u = 0; u < Uu; u++) {
        qA[u] = __float2half2_rn(qsm[w * 32 + u]);
        qB[u] = __float2half2_rn(qsm[(w + 8) * 32 + u]);
    }
    __half2 ba2 = __float2half2_rn(ba[0]);
    __half2 mA2 = __float2half2_rn(-60000.f), mB2 = mA2;
    __half2 z2  = __float2half2_rn(0.f);
    float sA = 0.f, sB = 0.f;
    float vAf = 0.f, vBf = 0.f;                    // lane owns channel c = lane

    const uint4* ksrc = (const uint4*)g_kh_u + (size_t)b * (Uu * Tt / 8);
    const uint4* xsrc = (const uint4*)g_xh_u + (size_t)b * (Cc * Tt / 8);
    unsigned* erowA = g_e_u + rowA * (Tt / 2);
    unsigned* erowB = g_e_u + rowB * (Tt / 2);

    for (int ch = 0; ch < NCH; ch++) {
        __syncthreads();
        for (int idx = tid; idx < 32 * 32; idx += 256) {
            int r = idx >> 5, g = idx & 31;
            ((uint4*)khs)[r * 32 + g] = ksrc[r * 128 + ch * 32 + g];
            ((uint4*)xhs)[r * 32 + g] = xsrc[r * 128 + ch * 32 + g];
        }
        __syncthreads();

        // ---- e-phase: 2 rows share every k-tile load ----
        #pragma unroll
        for (int jt = 0; jt < 4; jt++) {
            int pj = jt * 32 + lane;
            __half2 a0 = z2, a1 = z2, b0 = z2, b1h = z2;
            #pragma unroll
            for (int u = 0; u < Uu; u += 2) {
                __half2 k0 = khs[u][pj], k1 = khs[u + 1][pj];
                __half2 w0 = was[u], w1 = was[u + 1];
                a0  = __hfma2(w0, tanh2(__hadd2(qA[u],     k0)), a0);
                b0  = __hfma2(w0, tanh2(__hadd2(qB[u],     k0)), b0);
                a1  = __hfma2(w1, tanh2(__hadd2(qA[u + 1], k1)), a1);
                b1h = __hfma2(w1, tanh2(__hadd2(qB[u + 1], k1)), b1h);
            }
            __half2 eA2 = __hadd2(__hadd2(a0, a1), ba2);
            __half2 eB2 = __hadd2(__hadd2(b0, b1h), ba2);
            mA2 = __hmax2(mA2, eA2);
            mB2 = __hmax2(mB2, eB2);
            erowA[ch * PCH + pj] = h22u(eA2);
            erowB[ch * PCH + pj] = h22u(eB2);
            float2 fa = __half22float2(eA2);
            float2 fb = __half22float2(eB2);
            float pax = __expf(fa.x), pay = __expf(fa.y);
            float pbx = __expf(fb.x), pby = __expf(fb.y);
            sA += pax + pay; sB += pbx + pby;
            psm[w * PCH + pj]       = __floats2half2_rn(pax, pay);
            psm[(w + 8) * PCH + pj] = __floats2half2_rn(pbx, pby);
        }
        __syncwarp();

        // ---- v-phase: lane owns c = lane; rotation (q+lane)&127 => conflict-free
        #pragma unroll
        for (int qq = 0; qq < 4; qq++) {
            __half2 va = z2, vb = z2;
            #pragma unroll
            for (int q2i = 0; q2i < 32; q2i++) {
                int jj = ((qq * 32 + q2i) + lane) & (PCH - 1);
                __half2 xv = xhs[lane][jj];
                va = __hfma2(psm[w * PCH + jj],       xv, va);
                vb = __hfma2(psm[(w + 8) * PCH + jj], xv, vb);
            }
            float2 f = __half22float2(va); vAf += f.x + f.y;
            f = __half22float2(vb);        vBf += f.x + f.y;
        }
    }

    // ---- reductions ----
    #pragma unroll
    for (int off = 16; off; off >>= 1) {
        sA += __shfl_xor_sync(0xffffffffu, sA, off);
        sB += __shfl_xor_sync(0xffffffffu, sB, off);
    }
    float mAv = fmaxf(__low2float(mA2), __high2float(mA2));
    float mBv = fmaxf(__low2float(mB2), __high2float(mB2));
    #pragma unroll
    for (int off = 16; off; off >>= 1) {
        mAv = fmaxf(mAv, __shfl_xor_sync(0xffffffffu, mAv, off));
        mBv = fmaxf(mBv, __shfl_xor_sync(0xffffffffu, mBv, off));
    }
    float invA = 1.f / (sA + 1e-5f * __expf(mAv));
    float invB = 1.f / (sB + 1e-5f * __expf(mBv));

    // ---- LN1 (lane = channel) -> ys ----
    const float* xb = x + (size_t)b * Cc * Tt + (size_t)lane * Tt;
    #pragma unroll
    for (int r = 0; r < 2; r++) {
        int t   = (r == 0) ? tA : tB;
        int tok = (r == 0) ? w : (w + 8);
        float z = xb[t] + ((r == 0) ? vAf * invA : vBf * invB);
        float sum = z;
        #pragma unroll
        for (int off = 16; off; off >>= 1)
            sum += __shfl_xor_sync(0xffffffffu, sum, off);
        float mean = sum * (1.f / Cc);
        float d = z - mean;
        float vv = d * d;
        #pragma unroll
        for (int off = 16; off; off >>= 1)
            vv += __shfl_xor_sync(0xffffffffu, vv, off);
        float rstd = rsqrtf(vv * (1.f / Cc) + 1e-14f);
        ys[tok * 33 + lane] = d * rstd * g1[lane] + be1[lane];
    }
    __syncwarp();

    // ---- FF (intra-warp, tokens w and w+8) ----
    float acc[4][2];
    #pragma unroll
    for (int k = 0; k < 4; k++) {
        float bb = b1s[lane + 32 * k];
        acc[k][0] = bb; acc[k][1] = bb;
    }
    #pragma unroll
    for (int c = 0; c < Cc; c++) {
        float yv0 = ys[w * 33 + c];
        float yv1 = ys[(w + 8) * 33 + c];
        #pragma unroll
        for (int k = 0; k < 4; k++) {
            float wv = W1T[c * 129 + lane + 32 * k];
            acc[k][0] += yv0 * wv;
            acc[k][1] += yv1 * wv;
        }
    }
    #pragma unroll
    for (int k = 0; k < 4; k++) {
        h1s[w * 132 + lane + 32 * k]       = fmaxf(acc[k][0], 0.f);
        h1s[(w + 8) * 132 + lane + 32 * k] = fmaxf(acc[k][1], 0.f);
    }
    __syncwarp();

    float a2[2] = {0.f, 0.f};
    #pragma unroll 4
    for (int h = 0; h < Hh; h++) {
        float wv = W2p[lane * 129 + h];
        a2[0] += h1s[w * 132 + h] * wv;
        a2[1] += h1s[(w + 8) * 132 + h] * wv;
    }

    #pragma unroll
    for (int tk = 0; tk < 2; tk++) {
        int tok = (tk == 0) ? w : (w + 8);
        int t = t0 + tok;
        float z = ys[tok * 33 + lane] + a2[tk] + b2s[lane];
        float sum = z;
        #pragma unroll
        for (int off = 16; off; off >>= 1)
            sum += __shfl_xor_sync(0xffffffffu, sum, off);
        float mean = sum * (1.f / Cc);
        float d = z - mean;
        float vv = d * d;
        #pragma unroll
        for (int off = 16; off; off >>= 1)
            vv += __shfl_xor_sync(0xffffffffu, vv, off);
        float rstd = rsqrtf(vv * (1.f / Cc) + 1e-14f);
        y2[(size_t)b * Cc * Tt + (size_t)lane * Tt + t] = d * rstd * g2s[lane] + be2s[lane];
    }

    // ---- normalized-a write (e rows are L2-hot; same-thread RAW on g_e) ----
    float* arA = a_out + rowA * Tt;
    float* arB = a_out + rowB * Tt;
    #pragma unroll
    for (int q = 0; q < 16; q++) {
        int idx = q * 32 + lane;
        float2 fa = __half22float2(u2h2(erowA[idx]));
        float2 fb = __half22float2(u2h2(erowB[idx]));
        ((float2*)arA)[idx] = make_float2(__expf(fa.x) * invA, __expf(fa.y) * invA);
        ((float2*)arB)[idx] = make_float2(__expf(fb.x) * invB, __expf(fb.y) * invB);
    }
}

// ---------------------------------------------------------------------------
extern "C" void kernel_launch(void* const* d_in, const int* in_sizes, int n_in,
                              void* d_out, int out_size) {
    (void)in_sizes; (void)n_in; (void)out_size;
    const float* x   = (const float*)d_in[0];
    const float* Wt  = (const float*)d_in[1];
    const float* Wx  = (const float*)d_in[2];
    const float* bh  = (const float*)d_in[3];
    const float* Wa  = (const float*)d_in[4];
    const float* ba  = (const float*)d_in[5];
    const float* g1  = (const float*)d_in[6];
    const float* be1 = (const float*)d_in[7];
    const float* W1  = (const float*)d_in[8];
    const float* b1  = (const float*)d_in[9];
    const float* W2  = (const float*)d_in[10];
    const float* b2  = (const float*)d_in[11];
    const float* g2  = (const float*)d_in[12];
    const float* be2 = (const float*)d_in[13];

    float* out = (float*)d_out;
    float* y2  = out;                    // (B,C,T) = 131072 floats
    float* a   = out + Bq * Cc * Tt;     // (B,T,T) = 4194304 floats

    cudaFuncSetAttribute(k_main, cudaFuncAttributeMaxDynamicSharedMemorySize, SMEM_MAIN);

    k_prep<<<Bq * (Tt / 32), 256>>>(x, Wt, Wx, bh);
    k_main<<<Bq * (Tt / 16), 256, SMEM_MAIN>>>(x, a, Wa, ba, g1, be1,
                                               W1, b1, W2, b2, g2, be2, y2);
}

// round 6
// speedup vs baseline: 1.7409x; 1.1777x over previous
#include <cuda_runtime.h>
#include <cuda_fp16.h>

#define Bq 4
#define Cc 32
#define Tt 1024
#define Uu 32
#define Hh 128
#define PCH 128                 // half2 pairs per j-chunk (256 j)
#define NCH 4                   // chunks

// Scratch — device globals (no allocations allowed).
__device__ float    g_qp[Bq * Tt * Uu];            // q + bh, (B,T,U) f32
__device__ unsigned g_kh_u[Bq * Uu * Tt / 2];      // k as f16, (B,U,T)
__device__ unsigned g_xh_u[Bq * Cc * Tt / 2];      // x as f16, (B,C,T)
__device__ unsigned g_e_u [Bq * Tt * (Tt / 2)];    // raw scores e as f16, (B,T,T)
__device__ float    g_rm[Bq * Tt];                 // per-row max of e

__device__ __forceinline__ __half2 tanh2(__half2 x) {
    unsigned xi = *reinterpret_cast<unsigned*>(&x), ri;
    asm("tanh.approx.f16x2 %0, %1;" : "=r"(ri) : "r"(xi));
    return *reinterpret_cast<__half2*>(&ri);
}
__device__ __forceinline__ __half2 u2h2(unsigned u) { return *reinterpret_cast<__half2*>(&u); }
__device__ __forceinline__ unsigned h22u(__half2 h) { return *reinterpret_cast<unsigned*>(&h); }

// ---------------------------------------------------------------------------
// k_prep: 32 tokens/block, grid = B*(T/32) = 128, 256 threads.
// ---------------------------------------------------------------------------
__global__ void __launch_bounds__(256) k_prep(const float* __restrict__ x,
                                              const float* __restrict__ Wt,
                                              const float* __restrict__ Wx,
                                              const float* __restrict__ bh) {
    __shared__ float xs[Cc][32];
    __shared__ float Wts[Cc][33];
    __shared__ float Wxs[Cc][33];
    __shared__ float bhs[Uu];
    __shared__ __half kts[Uu][34];

    int b  = blockIdx.x >> 5;
    int t0 = (blockIdx.x & 31) * 32;
    int tid = threadIdx.x;
    int u = tid & 31, tlg = tid >> 5;

    for (int i = tid; i < Cc * 32; i += 256) {
        int c = i >> 5, tl = i & 31;
        xs[c][tl] = x[b * Cc * Tt + c * Tt + t0 + tl];
    }
    for (int i = tid; i < Cc * Uu; i += 256) {
        int c = i >> 5, uu = i & 31;
        Wts[c][uu] = Wt[i];
        Wxs[c][uu] = Wx[i];
    }
    if (tid < Uu) bhs[tid] = bh[tid];
    __syncthreads();

    #pragma unroll
    for (int rep = 0; rep < 4; rep++) {
        int tl = tlg + rep * 8;
        float accq = bhs[u], acck = 0.f;
        #pragma unroll
        for (int c = 0; c < Cc; c++) {
            float xv = xs[c][tl];
            accq += xv * Wts[c][u];
            acck += xv * Wxs[c][u];
        }
        g_qp[(b * Tt + t0 + tl) * Uu + u] = accq;
        kts[u][tl] = __float2half(acck);
    }
    __syncthreads();

    {
        int r = tid >> 3, g = tid & 7;
        __half* kh = (__half*)g_kh_u;
        __half* xh = (__half*)g_xh_u;
        unsigned* khrow = (unsigned*)(kh + (size_t)b * Uu * Tt + (size_t)r * Tt + t0);
        khrow[2 * g]     = *(unsigned*)&kts[r][4 * g];
        khrow[2 * g + 1] = *(unsigned*)&kts[r][4 * g + 2];
        unsigned* xhrow = (unsigned*)(xh + (size_t)b * Cc * Tt + (size_t)r * Tt + t0);
        __half2 h0 = __floats2half2_rn(xs[r][4 * g],     xs[r][4 * g + 1]);
        __half2 h1 = __floats2half2_rn(xs[r][4 * g + 2], xs[r][4 * g + 3]);
        xhrow[2 * g]     = h22u(h0);
        xhrow[2 * g + 1] = h22u(h1);
    }
}

// ---------------------------------------------------------------------------
// k_scores: hybrid MUFU/poly tanh. 1 row/warp, grid = B*(T/8) = 512, 256 thr.
// Even u -> tanh.approx.f16x2 (MUFU); odd u -> degree-5 poly (FMA pipe).
// Writes raw e (f16) to g_e and per-row max to g_rm.
// ---------------------------------------------------------------------------
__global__ void __launch_bounds__(256, 3) k_scores(const float* __restrict__ Wa,
                                                   const float* __restrict__ ba) {
    __shared__ __half2 khs[Uu][PCH];   // 16KB
    __shared__ __half2 qsm2[8][33];

    int b  = blockIdx.x / (Tt / 8);
    int i0 = (blockIdx.x % (Tt / 8)) * 8;
    int tid = threadIdx.x, w = tid >> 5, lane = tid & 31;
    int i = i0 + w;
    size_t row = (size_t)b * Tt + i;

    qsm2[tid >> 5][tid & 31] =
        __float2half2_rn(g_qp[((size_t)b * Tt + i0 + (tid >> 5)) * Uu + (tid & 31)]);

    __half2 wa2[Uu];
    #pragma unroll
    for (int u = 0; u < Uu; u++) wa2[u] = __float2half2_rn(Wa[u]);
    __half2 ba2  = __float2half2_rn(ba[0]);
    __half2 m2   = __float2half2_rn(-60000.f);
    __half2 z2   = __float2half2_rn(0.f);
    __half2 one2 = __float2half2_rn(1.f);
    __half2 ca2  = __float2half2_rn(-1.f / 3.f);
    __half2 cb2  = __float2half2_rn(2.f / 15.f);

    const uint4* kb4 = (const uint4*)g_kh_u + (size_t)b * (Uu * Tt / 8);
    unsigned* erow = g_e_u + row * (Tt / 2);
    __syncthreads();

    for (int ch = 0; ch < NCH; ch++) {
        __syncthreads();
        #pragma unroll
        for (int k = 0; k < 4; k++) {
            int idx = tid + k * 256;               // 1024 uint4 total
            int r = idx >> 5, g = idx & 31;
            ((uint4*)khs)[idx] = kb4[r * 128 + ch * 32 + g];
        }
        __syncthreads();

        #pragma unroll
        for (int jt = 0; jt < 4; jt++) {
            int pj = jt * 32 + lane;
            __half2 acc0 = z2, acc1 = z2;
            #pragma unroll
            for (int u = 0; u < Uu; u += 2) {
                // even u: MUFU tanh
                __half2 xm = __hadd2(qsm2[w][u], khs[u][pj]);
                acc0 = __hfma2(wa2[u], tanh2(xm), acc0);
                // odd u: poly on FMA pipe
                __half2 xp = __hadd2(qsm2[w][u + 1], khs[u + 1][pj]);
                __half2 x2 = __hmul2(xp, xp);
                __half2 tp = __hfma2(x2, cb2, ca2);
                tp = __hfma2(x2, tp, one2);
                acc1 = __hfma2(wa2[u + 1], __hmul2(xp, tp), acc1);
            }
            __half2 e2 = __hadd2(__hadd2(acc0, acc1), ba2);
            m2 = __hmax2(m2, e2);
            erow[ch * PCH + pj] = h22u(e2);
        }
    }

    float m = fmaxf(__low2float(m2), __high2float(m2));
    #pragma unroll
    for (int off = 16; off; off >>= 1)
        m = fmaxf(m, __shfl_xor_sync(0xffffffffu, m, off));
    if (lane == 0) g_rm[row] = m;
}

// ---------------------------------------------------------------------------
// Fused k_av_ff (R4, known-good): softmax-apply + LN1 + FF + LN2 + a-write.
// ---------------------------------------------------------------------------
#define OFF_XT   0                          // __half2 xh2s[Cc][256]   32768 B
#define OFF_W1T  32768                      // float W1T[Cc*129]       16512 B
#define OFF_W2P  (OFF_W1T + 16512)          // float W2p[Cc*129]       16512 B
#define OFF_YS   (OFF_W2P + 16512)          // float ys[16*33]          2112 B
#define OFF_H1   (OFF_YS + 2112)            // float h1s[16*132]        8448 B
#define OFF_B1   (OFF_H1 + 8448)            // float b1s[128]            512 B
#define OFF_B2   (OFF_B1 + 512)             // float b2s[32]             128 B
#define OFF_G2   (OFF_B2 + 128)             // float g2s[32]             128 B
#define OFF_BE2  (OFF_G2 + 128)             // float be2s[32]            128 B
#define SMEM_AVFF (OFF_BE2 + 128)           // 77056 B

__global__ void __launch_bounds__(256) k_av_ff(const float* __restrict__ x,
                                               float* __restrict__ a_out,
                                               const float* __restrict__ g1,
                                               const float* __restrict__ be1,
                                               const float* __restrict__ W1,
                                               const float* __restrict__ b1,
                                               const float* __restrict__ W2,
                                               const float* __restrict__ b2,
                                               const float* __restrict__ g2,
                                               const float* __restrict__ be2,
                                               float* __restrict__ y2) {
    extern __shared__ char dyn[];
    __half2 (*xh2s)[256] = (__half2 (*)[256])(dyn + OFF_XT);
    float* W1T  = (float*)(dyn + OFF_W1T);
    float* W2p  = (float*)(dyn + OFF_W2P);
    float* ys   = (float*)(dyn + OFF_YS);
    float* h1s  = (float*)(dyn + OFF_H1);
    float* b1s  = (float*)(dyn + OFF_B1);
    float* b2s  = (float*)(dyn + OFF_B2);
    float* g2s  = (float*)(dyn + OFF_G2);
    float* be2s = (float*)(dyn + OFF_BE2);

    int b  = blockIdx.x / (Tt / 16);
    int t0 = (blockIdx.x % (Tt / 16)) * 16;
    int tid = threadIdx.x, w = tid >> 5, lane = tid & 31;
    int tA = t0 + 2 * w, tB = tA + 1;
    size_t rowA = (size_t)b * Tt + tA, rowB = rowA + 1;

    for (int i = tid; i < Hh * Cc; i += 256) {
        int h = i >> 5, c = i & 31;
        W1T[c * 129 + h] = W1[i];
        int c2 = i >> 7, h2 = i & 127;
        W2p[c2 * 129 + h2] = W2[i];
    }
    if (tid < Hh) b1s[tid] = b1[tid];
    if (tid < Cc) { b2s[tid] = b2[tid]; g2s[tid] = g2[tid]; be2s[tid] = be2[tid]; }

    const unsigned* eAu = g_e_u + rowA * (Tt / 2);
    const unsigned* eBu = g_e_u + rowB * (Tt / 2);
    const uint4* eA4 = (const uint4*)eAu;
    const uint4* eB4 = (const uint4*)eBu;

    float sA = 0.f, sB = 0.f;
    __half2 zero2 = __float2half2_rn(0.f);
    __half2 vA[Cc], vB[Cc];
    #pragma unroll
    for (int c = 0; c < Cc; c++) { vA[c] = zero2; vB[c] = zero2; }

    for (int chunk = 0; chunk < 2; chunk++) {
        __syncthreads();
        for (int idx = tid; idx < Cc * 64; idx += 256) {
            int c = idx >> 6, g = idx & 63;
            ((uint4*)xh2s)[c * 64 + g] =
                ((const uint4*)g_xh_u)[(size_t)b * Cc * Tt / 8 + c * 128 + chunk * 64 + g];
        }
        __syncthreads();

        #pragma unroll
        for (int q = 0; q < 2; q++) {
            int g   = chunk * 64 + q * 32 + lane;
            int lp4 = q * 32 + lane;
            uint4 ea = eA4[g], eb = eB4[g];
            unsigned eua[4] = {ea.x, ea.y, ea.z, ea.w};
            unsigned eub[4] = {eb.x, eb.y, eb.z, eb.w};
            __half2 pA[4], pB[4];
            #pragma unroll
            for (int r = 0; r < 4; r++) {
                float2 fa = __half22float2(u2h2(eua[r]));
                float2 fb = __half22float2(u2h2(eub[r]));
                float pax = __expf(fa.x), pay = __expf(fa.y);
                float pbx = __expf(fb.x), pby = __expf(fb.y);
                sA += pax + pay; sB += pbx + pby;
                pA[r] = __floats2half2_rn(pax, pay);
                pB[r] = __floats2half2_rn(pbx, pby);
            }
            #pragma unroll
            for (int c = 0; c < Cc; c++) {
                uint4 xv = ((const uint4*)&xh2s[c][0])[lp4];
                vA[c] = __hfma2(pA[0], u2h2(xv.x), vA[c]);
                vA[c] = __hfma2(pA[1], u2h2(xv.y), vA[c]);
                vA[c] = __hfma2(pA[2], u2h2(xv.z), vA[c]);
                vA[c] = __hfma2(pA[3], u2h2(xv.w), vA[c]);
                vB[c] = __hfma2(pB[0], u2h2(xv.x), vB[c]);
                vB[c] = __hfma2(pB[1], u2h2(xv.y), vB[c]);
                vB[c] = __hfma2(pB[2], u2h2(xv.z), vB[c]);
                vB[c] = __hfma2(pB[3], u2h2(xv.w), vB[c]);
            }
        }
    }

    float vfA[Cc], vfB[Cc];
    #pragma unroll
    for (int c = 0; c < Cc; c++) {
        float2 fa = __half22float2(vA[c]); vfA[c] = fa.x + fa.y;
        float2 fb = __half22float2(vB[c]); vfB[c] = fb.x + fb.y;
    }

    #pragma unroll
    for (int off = 16; off; off >>= 1) {
        sA += __shfl_xor_sync(0xffffffffu, sA, off);
        sB += __shfl_xor_sync(0xffffffffu, sB, off);
    }
    float invA = 1.f / (sA + 1e-5f * __expf(g_rm[rowA]));
    float invB = 1.f / (sB + 1e-5f * __expf(g_rm[rowB]));

    float mineA = 0.f, mineB = 0.f;
    #pragma unroll
    for (int c = 0; c < Cc; c++) {
        float ta = vfA[c], tb = vfB[c];
        #pragma unroll
        for (int off = 16; off; off >>= 1) {
            ta += __shfl_xor_sync(0xffffffffu, ta, off);
            tb += __shfl_xor_sync(0xffffffffu, tb, off);
        }
        if (lane == c) { mineA = ta; mineB = tb; }
    }

    const float* xb = x + (size_t)b * Cc * Tt + (size_t)lane * Tt;
    #pragma unroll
    for (int r = 0; r < 2; r++) {
        int t = (r == 0) ? tA : tB;
        float z = xb[t] + ((r == 0) ? mineA * invA : mineB * invB);
        float sum = z;
        #pragma unroll
        for (int off = 16; off; off >>= 1)
            sum += __shfl_xor_sync(0xffffffffu, sum, off);
        float mean = sum * (1.f / Cc);
        float d = z - mean;
        float vv = d * d;
        #pragma unroll
        for (int off = 16; off; off >>= 1)
            vv += __shfl_xor_sync(0xffffffffu, vv, off);
        float rstd = rsqrtf(vv * (1.f / Cc) + 1e-14f);
        ys[(2 * w + r) * 33 + lane] = d * rstd * g1[lane] + be1[lane];
    }
    __syncwarp();

    int tokbase = 2 * w;
    float acc[4][2];
    #pragma unroll
    for (int k = 0; k < 4; k++) {
        float bb = b1s[lane + 32 * k];
        acc[k][0] = bb; acc[k][1] = bb;
    }
    #pragma unroll
    for (int c = 0; c < Cc; c++) {
        float yv0 = ys[tokbase * 33 + c];
        float yv1 = ys[(tokbase + 1) * 33 + c];
        #pragma unroll
        for (int k = 0; k < 4; k++) {
            float wv = W1T[c * 129 + lane + 32 * k];
            acc[k][0] += yv0 * wv;
            acc[k][1] += yv1 * wv;
        }
    }
    #pragma unroll
    for (int k = 0; k < 4; k++) {
        h1s[tokbase * 132 + lane + 32 * k]       = fmaxf(acc[k][0], 0.f);
        h1s[(tokbase + 1) * 132 + lane + 32 * k] = fmaxf(acc[k][1], 0.f);
    }
    __syncwarp();

    float a2[2] = {0.f, 0.f};
    #pragma unroll 4
    for (int h = 0; h < Hh; h++) {
        float wv = W2p[lane * 129 + h];
        a2[0] += h1s[tokbase * 132 + h] * wv;
        a2[1] += h1s[(tokbase + 1) * 132 + h] * wv;
    }

    #pragma unroll
    for (int tk = 0; tk < 2; tk++) {
        int tok = tokbase + tk;
        int t = t0 + tok;
        float z = ys[tok * 33 + lane] + a2[tk] + b2s[lane];
        float sum = z;
        #pragma unroll
        for (int off = 16; off; off >>= 1)
            sum += __shfl_xor_sync(0xffffffffu, sum, off);
        float mean = sum * (1.f / Cc);
        float d = z - mean;
        float vv = d * d;
        #pragma unroll
        for (int off = 16; off; off >>= 1)
            vv += __shfl_xor_sync(0xffffffffu, vv, off);
        float rstd = rsqrtf(vv * (1.f / Cc) + 1e-14f);
        y2[(size_t)b * Cc * Tt + (size_t)lane * Tt + t] = d * rstd * g2s[lane] + be2s[lane];
    }

    float* arowA = a_out + rowA * Tt;
    float* arowB = a_out + rowB * Tt;
    #pragma unroll
    for (int q = 0; q < 16; q++) {
        int idx = q * 32 + lane;
        float2 fa = __half22float2(u2h2(eAu[idx]));
        float2 fb = __half22float2(u2h2(eBu[idx]));
        ((float2*)arowA)[idx] = make_float2(__expf(fa.x) * invA, __expf(fa.y) * invA);
        ((float2*)arowB)[idx] = make_float2(__expf(fb.x) * invB, __expf(fb.y) * invB);
    }
}

// ---------------------------------------------------------------------------
extern "C" void kernel_launch(void* const* d_in, const int* in_sizes, int n_in,
                              void* d_out, int out_size) {
    (void)in_sizes; (void)n_in; (void)out_size;
    const float* x   = (const float*)d_in[0];
    const float* Wt  = (const float*)d_in[1];
    const float* Wx  = (const float*)d_in[2];
    const float* bh  = (const float*)d_in[3];
    const float* Wa  = (const float*)d_in[4];
    const float* ba  = (const float*)d_in[5];
    const float* g1  = (const float*)d_in[6];
    const float* be1 = (const float*)d_in[7];
    const float* W1  = (const float*)d_in[8];
    const float* b1  = (const float*)d_in[9];
    const float* W2  = (const float*)d_in[10];
    const float* b2  = (const float*)d_in[11];
    const float* g2  = (const float*)d_in[12];
    const float* be2 = (const float*)d_in[13];

    float* out = (float*)d_out;
    float* y2  = out;                    // (B,C,T) = 131072 floats
    float* a   = out + Bq * Cc * Tt;     // (B,T,T) = 4194304 floats

    cudaFuncSetAttribute(k_av_ff, cudaFuncAttributeMaxDynamicSharedMemorySize, SMEM_AVFF);

    k_prep  <<<Bq * (Tt / 32), 256>>>(x, Wt, Wx, bh);
    k_scores<<<Bq * (Tt / 8),  256>>>(Wa, ba);
    k_av_ff <<<Bq * (Tt / 16), 256, SMEM_AVFF>>>(x, a, g1, be1, W1, b1, W2, b2, g2, be2, y2);
}